// round 14
// baseline (speedup 1.0000x reference)
#include <cuda_runtime.h>
#include <cuda_bf16.h>
#include <stdint.h>

#define NPTS 200000
#define FINFO_MIN_F (-3.4028234663852886e38f)

typedef unsigned long long ull;

// ---------------- scratch (device globals; no allocs allowed) ----------------
__device__ float g_stats[100000 * 8];            // per (scale,voxel): sums x,y,z,w, vlx,vly, cnt, pad
__device__ int   g_cur[100000];                  // per (scale,voxel) point counter
__device__ int   g_plist[4800000];               // fixed-capacity point lists per (scale,voxel)
__device__ float g_P[70000 * 128];               // per-voxel vf @ W_o slice
__device__ float g_final[(size_t)200064 * 192];  // final0|final1|final2 per point (padded)
__device__ float g_pfco[(size_t)NPTS * 128];     // feat @ W_avfeo_point
__device__ uint4 g_Bcvt[7680];                   // Wo(final rows) as bf16 hi/lo smem images, 6 chunks

// ---------------- f32x2 / RED helpers ----------------
__device__ __forceinline__ ull dup2(float x) {
    ull r; asm("mov.b64 %0,{%1,%1};" : "=l"(r) : "f"(x)); return r;
}
__device__ __forceinline__ ull pk2(float x, float y) {
    ull r; asm("mov.b64 %0,{%1,%2};" : "=l"(r) : "f"(x), "f"(y)); return r;
}
__device__ __forceinline__ void fma2(ull& d, ull a, ull b) {
    asm("fma.rn.f32x2 %0,%1,%2,%0;" : "+l"(d) : "l"(a), "l"(b));
}
__device__ __forceinline__ ull mul2(ull a, ull b) {
    ull d; asm("mul.rn.f32x2 %0,%1,%2;" : "=l"(d) : "l"(a), "l"(b)); return d;
}
__device__ __forceinline__ void up2(float& x, float& y, ull a) {
    asm("mov.b64 {%0,%1},%2;" : "=f"(x), "=f"(y) : "l"(a));
}
__device__ __forceinline__ void redadd4(float* p, float a, float b, float c, float d) {
    asm volatile("red.global.add.v4.f32 [%0], {%1,%2,%3,%4};"
                 :: "l"(__cvta_generic_to_global(p)), "f"(a), "f"(b), "f"(c), "f"(d) : "memory");
}

// ---------------- mma / cp.async helpers ----------------
__device__ __forceinline__ uint32_t smem_u32(const void* p) {
    uint32_t a;
    asm("{ .reg .u64 t; cvta.to.shared.u64 t, %1; cvt.u32.u64 %0, t; }" : "=r"(a) : "l"(p));
    return a;
}
__device__ __forceinline__ void ldsm4(uint32_t* r, uint32_t addr) {
    asm volatile("ldmatrix.sync.aligned.m8n8.x4.shared.b16 {%0,%1,%2,%3}, [%4];"
                 : "=r"(r[0]), "=r"(r[1]), "=r"(r[2]), "=r"(r[3]) : "r"(addr));
}
__device__ __forceinline__ void mma_bf16(float* d, const uint32_t* a, uint32_t b0, uint32_t b1) {
    asm volatile(
        "mma.sync.aligned.m16n8k16.row.col.f32.bf16.bf16.f32 "
        "{%0,%1,%2,%3}, {%4,%5,%6,%7}, {%8,%9}, {%0,%1,%2,%3};"
        : "+f"(d[0]), "+f"(d[1]), "+f"(d[2]), "+f"(d[3])
        : "r"(a[0]), "r"(a[1]), "r"(a[2]), "r"(a[3]), "r"(b0), "r"(b1));
}
__device__ __forceinline__ void cpasync16(uint32_t smaddr, const void* g) {
    asm volatile("cp.async.ca.shared.global [%0], [%1], 16;"
                 :: "r"(smaddr), "l"(g) : "memory");
}
#define CP_COMMIT() asm volatile("cp.async.commit_group;" ::: "memory")
#define CP_WAIT0()  asm volatile("cp.async.wait_group 0;" ::: "memory")

__device__ __forceinline__ void cvt8(const float* x, uint4& hi, uint4& lo) {
    unsigned h[4], l[4];
    #pragma unroll
    for (int i = 0; i < 4; i++) {
        __nv_bfloat162 hb = __floats2bfloat162_rn(x[2 * i], x[2 * i + 1]);
        float f0 = __bfloat162float(hb.x), f1 = __bfloat162float(hb.y);
        __nv_bfloat162 lb = __floats2bfloat162_rn(x[2 * i] - f0, x[2 * i + 1] - f1);
        h[i] = *(unsigned*)&hb;
        l[i] = *(unsigned*)&lb;
    }
    hi.x = h[0]; hi.y = h[1]; hi.z = h[2]; hi.w = h[3];
    lo.x = l[0]; lo.y = l[1]; lo.z = l[2]; lo.w = l[3];
}

struct Ptrs {
    const float* vlc[5];
    const int*   pv[5];
};

// per-scale layout: soff {0,40000,60000,70000,90000}, cap {32,48,80,48,80},
// pbase {0,1280000,2240000,3040000,4000000}

// ---------------- per-voxel sums + point-list fill, all 5 scales ----------------
__global__ __launch_bounds__(256) void k_statsfill(const float4* __restrict__ pts, Ptrs io) {
    int p = blockIdx.x * 256 + threadIdx.x;
    if (p >= NPTS) return;
    float4 q = pts[p];
    const int soffs[5]  = {0, 40000, 60000, 70000, 90000};
    const int caps[5]   = {32, 48, 80, 48, 80};
    const int pbases[5] = {0, 1280000, 2240000, 3040000, 4000000};
    #pragma unroll
    for (int i = 0; i < 5; i++) {
        int v = io.pv[i][p];
        float vx = io.vlc[i][3 * p], vy = io.vlc[i][3 * p + 1];
        float* s = &g_stats[(size_t)(soffs[i] + v) * 8];
        redadd4(s, q.x, q.y, q.z, q.w);
        redadd4(s + 4, vx, vy, 1.0f, 0.0f);
        int slot = atomicAdd(&g_cur[soffs[i] + v], 1);
        if (slot < caps[i]) g_plist[pbases[i] + v * caps[i] + slot] = p;
    }
}

// ---------------- Wo(final rows) -> bf16 hi/lo smem image, once ----------------
__global__ __launch_bounds__(256) void k_wcvt(const float* __restrict__ Wo) {
    int idx = blockIdx.x * 256 + threadIdx.x;
    if (idx >= 192 * 128) return;
    int kk = idx >> 7, n = idx & 127;
    int kc = kk >> 5, ko = kk & 31;
    int r = ((kk >> 6) << 7) + (kk & 63);     // rows {0..63,128..191,256..319}
    float v = Wo[(size_t)r * 128 + n];
    __nv_bfloat16 hb = __float2bfloat16_rn(v);
    __nv_bfloat16 lb = __float2bfloat16_rn(v - __bfloat162float(hb));
    char* base = (char*)g_Bcvt + kc * 20480 + n * 80 + ko * 2;
    *(__nv_bfloat16*)base = hb;
    *(__nv_bfloat16*)(base + 10240) = lb;
}

// ---------------- scales 0..2: folded-basis dual GEMV + product -> g_final ----------------
__global__ __launch_bounds__(256) void k_avfe(const float4* __restrict__ pts, Ptrs io,
                                              const float* __restrict__ Wp,
                                              const float* __restrict__ Wa) {
    __shared__ float sP[9 * 64];
    __shared__ float sA[12 * 64];
    const int tid = threadIdx.x;
    if (tid < 64) {
        const int c = tid;
        float w0 = Wp[c], w1 = Wp[64 + c], w2 = Wp[128 + c], w3 = Wp[192 + c];
        float w4 = Wp[256 + c], w5 = Wp[320 + c], w6 = Wp[384 + c], w7 = Wp[448 + c], w8 = Wp[512 + c];
        sP[0 * 64 + c] = w0 + w4; sP[1 * 64 + c] = w1 + w5; sP[2 * 64 + c] = w2 + w6;
        sP[3 * 64 + c] = w3;
        sP[4 * 64 + c] = -w4; sP[5 * 64 + c] = -w5; sP[6 * 64 + c] = -w6;
        sP[7 * 64 + c] = w7; sP[8 * 64 + c] = w8;
        float a0 = Wa[c], a1 = Wa[64 + c], a2 = Wa[128 + c], a3 = Wa[192 + c];
        float a4 = Wa[256 + c], a5 = Wa[320 + c], a6 = Wa[384 + c];
        float a7 = Wa[448 + c], a8 = Wa[512 + c];
        float a9 = Wa[576 + c], a10 = Wa[640 + c], a11 = Wa[704 + c], a12 = Wa[768 + c];
        float a16 = Wa[1024 + c], a17 = Wa[1088 + c];
        float L0 = a0 + a4, L1 = a1 + a5, L2 = a2 + a6;
        sA[0 * 64 + c] = L0; sA[1 * 64 + c] = L1; sA[2 * 64 + c] = L2; sA[3 * 64 + c] = a3;
        sA[4 * 64 + c] = a9 - L0; sA[5 * 64 + c] = a10 - L1; sA[6 * 64 + c] = a11 - L2;
        sA[7 * 64 + c] = a12;
        sA[8 * 64 + c] = a7; sA[9 * 64 + c] = a8;
        sA[10 * 64 + c] = a16; sA[11 * 64 + c] = a17;
    }
    __syncthreads();
    const int p = blockIdx.x * 256 + tid;
    if (p >= NPTS) return;
    float4 q = pts[p];
    ull cqx = dup2(q.x), cqy = dup2(q.y), cqz = dup2(q.z), cqw = dup2(q.w);
    #pragma unroll
    for (int i = 0; i < 3; i++) {
        const int soff = (i == 0) ? 0 : ((i == 1) ? 40000 : 60000);
        int v = io.pv[i][p];
        float vlx = io.vlc[i][3 * p], vly = io.vlc[i][3 * p + 1];
        const float4* s4 = (const float4*)&g_stats[(size_t)(soff + v) * 8];
        float4 sa = s4[0], sb = s4[1];
        float inv = 1.0f / fmaxf(sb.z, 1.0f);
        ull cp4 = dup2(sa.x * inv), cp5 = dup2(sa.y * inv), cp6 = dup2(sa.z * inv), cp7 = dup2(sa.w * inv);
        ull cv0 = dup2(vlx), cv1 = dup2(vly);
        ull cm0 = dup2(sb.x * inv), cm1 = dup2(sb.y * inv);
        ull cp[9]  = {cqx, cqy, cqz, cqw, cp4, cp5, cp6, cv0, cv1};
        ull ca[12] = {cqx, cqy, cqz, cqw, cp4, cp5, cp6, cp7, cv0, cv1, cm0, cm1};
        float* fout = &g_final[(size_t)p * 192 + i * 64];
        #pragma unroll 2
        for (int c = 0; c < 64; c += 4) {
            ull p0 = 0, p1 = 0, a0 = 0, a1 = 0;
            #pragma unroll
            for (int r = 0; r < 9; r++) {
                ulonglong2 w = *(const ulonglong2*)&sP[r * 64 + c];
                fma2(p0, cp[r], w.x); fma2(p1, cp[r], w.y);
            }
            #pragma unroll
            for (int r = 0; r < 12; r++) {
                ulonglong2 w = *(const ulonglong2*)&sA[r * 64 + c];
                fma2(a0, ca[r], w.x); fma2(a1, ca[r], w.y);
            }
            ulonglong2 fo; fo.x = mul2(a0, p0); fo.y = mul2(a1, p1);
            *(ulonglong2*)&fout[c] = fo;
        }
    }
}

// ---------------- fused gather-max + GEMM: P = max_pts(final) @ W_o[vf-rows] ----------------
__global__ __launch_bounds__(256) void k_pvoxm(const float* __restrict__ Wo) {
    __shared__ float sA[64 * 68];
    const int b = blockIdx.x, tid = threadIdx.x;
    int voff, V, wrow, vb, cap, pbase, scoff;
    if (b < 625)      { voff = 0;     V = 40000; wrow = 64;  vb = b * 64;         cap = 32; pbase = 0;       scoff = 0; }
    else if (b < 938) { voff = 40000; V = 20000; wrow = 192; vb = (b - 625) * 64; cap = 48; pbase = 1280000; scoff = 64; }
    else              { voff = 60000; V = 10000; wrow = 320; vb = (b - 938) * 64; cap = 80; pbase = 2240000; scoff = 128; }
    {
        const int vl = tid >> 2, sub = tid & 3;
        const int v = vb + vl;
        float mx[16];
        #pragma unroll
        for (int c = 0; c < 16; c++) mx[c] = FINFO_MIN_F;
        if (v < V) {
            int cnt = g_cur[voff + v];
            if (cnt > cap) cnt = cap;
            const int* lst = &g_plist[pbase + v * cap];
            const int chb = sub * 16;
            int j = 0;
            for (; j + 2 <= cnt; j += 2) {
                int pA = lst[j], pB = lst[j + 1];
                const float4* fA = (const float4*)&g_final[(size_t)pA * 192 + scoff + chb];
                const float4* fB = (const float4*)&g_final[(size_t)pB * 192 + scoff + chb];
                float4 a0 = fA[0], a1 = fA[1], a2 = fA[2], a3 = fA[3];
                float4 b0 = fB[0], b1 = fB[1], b2 = fB[2], b3 = fB[3];
                mx[0] = fmaxf(mx[0], fmaxf(a0.x, b0.x)); mx[1] = fmaxf(mx[1], fmaxf(a0.y, b0.y));
                mx[2] = fmaxf(mx[2], fmaxf(a0.z, b0.z)); mx[3] = fmaxf(mx[3], fmaxf(a0.w, b0.w));
                mx[4] = fmaxf(mx[4], fmaxf(a1.x, b1.x)); mx[5] = fmaxf(mx[5], fmaxf(a1.y, b1.y));
                mx[6] = fmaxf(mx[6], fmaxf(a1.z, b1.z)); mx[7] = fmaxf(mx[7], fmaxf(a1.w, b1.w));
                mx[8] = fmaxf(mx[8], fmaxf(a2.x, b2.x)); mx[9] = fmaxf(mx[9], fmaxf(a2.y, b2.y));
                mx[10] = fmaxf(mx[10], fmaxf(a2.z, b2.z)); mx[11] = fmaxf(mx[11], fmaxf(a2.w, b2.w));
                mx[12] = fmaxf(mx[12], fmaxf(a3.x, b3.x)); mx[13] = fmaxf(mx[13], fmaxf(a3.y, b3.y));
                mx[14] = fmaxf(mx[14], fmaxf(a3.z, b3.z)); mx[15] = fmaxf(mx[15], fmaxf(a3.w, b3.w));
            }
            if (j < cnt) {
                int p = lst[j];
                const float4* f = (const float4*)&g_final[(size_t)p * 192 + scoff + chb];
                float4 x0 = f[0], x1 = f[1], x2 = f[2], x3 = f[3];
                mx[0] = fmaxf(mx[0], x0.x); mx[1] = fmaxf(mx[1], x0.y);
                mx[2] = fmaxf(mx[2], x0.z); mx[3] = fmaxf(mx[3], x0.w);
                mx[4] = fmaxf(mx[4], x1.x); mx[5] = fmaxf(mx[5], x1.y);
                mx[6] = fmaxf(mx[6], x1.z); mx[7] = fmaxf(mx[7], x1.w);
                mx[8] = fmaxf(mx[8], x2.x); mx[9] = fmaxf(mx[9], x2.y);
                mx[10] = fmaxf(mx[10], x2.z); mx[11] = fmaxf(mx[11], x2.w);
                mx[12] = fmaxf(mx[12], x3.x); mx[13] = fmaxf(mx[13], x3.y);
                mx[14] = fmaxf(mx[14], x3.z); mx[15] = fmaxf(mx[15], x3.w);
            }
        }
        const int chb = sub * 16;
        #pragma unroll
        for (int c = 0; c < 16; c++) sA[(chb + c) * 68 + vl] = mx[c];
    }
    __syncthreads();
    const int pg = tid >> 4, cg = tid & 15;
    const float* Wb = Wo + (size_t)wrow * 128 + cg * 8;
    ull acc[4][4] = {};
    #pragma unroll 8
    for (int k = 0; k < 64; k++) {
        float4 av = *(const float4*)&sA[k * 68 + pg * 4];
        ull a0 = dup2(av.x), a1 = dup2(av.y), a2 = dup2(av.z), a3 = dup2(av.w);
        const float* br = Wb + (size_t)k * 128;
        ulonglong2 b0 = *(const ulonglong2*)br;
        ulonglong2 b1 = *(const ulonglong2*)(br + 4);
        fma2(acc[0][0], a0, b0.x); fma2(acc[0][1], a0, b0.y); fma2(acc[0][2], a0, b1.x); fma2(acc[0][3], a0, b1.y);
        fma2(acc[1][0], a1, b0.x); fma2(acc[1][1], a1, b0.y); fma2(acc[1][2], a1, b1.x); fma2(acc[1][3], a1, b1.y);
        fma2(acc[2][0], a2, b0.x); fma2(acc[2][1], a2, b0.y); fma2(acc[2][2], a2, b1.x); fma2(acc[2][3], a2, b1.y);
        fma2(acc[3][0], a3, b0.x); fma2(acc[3][1], a3, b0.y); fma2(acc[3][2], a3, b1.x); fma2(acc[3][3], a3, b1.y);
    }
    #pragma unroll
    for (int m = 0; m < 4; m++) {
        int v = vb + pg * 4 + m;
        if (v < V) {
            float* dst = &g_P[(size_t)(voff + v) * 128 + cg * 8];
            ulonglong2 o0; o0.x = acc[m][0]; o0.y = acc[m][1];
            ulonglong2 o1; o1.x = acc[m][2]; o1.y = acc[m][3];
            *(ulonglong2*)dst = o0;
            *(ulonglong2*)(dst + 4) = o1;
        }
    }
}

// ---------------- main GEMM: mma.sync bf16 3-way split, K=192, 2x2 warp tile ----------------
// per buffer (40960 B): A_hi[128][40 bf16] @0, A_lo @10240, B_hi @20480, B_lo @30720
#define GBUF 40960

__device__ __forceinline__ void gemm_cvtstoreA(char* buf, const float* x, int srow, int sko) {
    uint4 h0, l0, h1, l1;
    cvt8(x, h0, l0); cvt8(x + 8, h1, l1);
    char* pa = buf + srow * 80 + sko * 2;
    *(uint4*)pa = h0;
    *(uint4*)(pa + 16) = h1;
    *(uint4*)(pa + 10240) = l0;
    *(uint4*)(pa + 10240 + 16) = l1;
}
__device__ __forceinline__ void gemm_loadA(float* x, int p0, int srow, int sko, int kc) {
    const float* src = &g_final[(size_t)(p0 + srow) * 192 + kc * 32 + sko];
    *(float4*)(x) = ((const float4*)src)[0];
    *(float4*)(x + 4) = ((const float4*)src)[1];
    *(float4*)(x + 8) = ((const float4*)src)[2];
    *(float4*)(x + 12) = ((const float4*)src)[3];
}
__device__ __forceinline__ void stageB_async(uint32_t dst, int kc, int tid) {
    const uint4* src = g_Bcvt + kc * 1280 + tid;
    #pragma unroll
    for (int i = 0; i < 5; i++)
        cpasync16(dst + (uint32_t)(tid + i * 256) * 16, src + i * 256);
}

__global__ __launch_bounds__(256, 2) void k_gemm(const int* __restrict__ pv0,
                                                 const int* __restrict__ pv1,
                                                 const int* __restrict__ pv2) {
    extern __shared__ __align__(16) char sm[];
    const int tid = threadIdx.x, lane = tid & 31, wid = tid >> 5;
    const int p0 = blockIdx.x * 128;
    const int mrow = (wid & 3) * 32;
    const int ncol = (wid >> 2) * 64;

    float acc[16][4] = {};
    const uint32_t abase = (uint32_t)((mrow + (lane & 15)) * 80 + ((lane >> 4) << 4));
    const uint32_t bbase = (uint32_t)(20480 + (ncol + (lane & 7) + ((lane >> 4) << 3)) * 80
                                      + ((lane & 8) << 1));
    const int srow = tid >> 1, sko = (tid & 1) * 16;

    float xa[16];
    {   // prologue: stage kc=0 (A cvt + B async), preload A(kc=1)
        float x0[16];
        gemm_loadA(x0, p0, srow, sko, 0);
        gemm_cvtstoreA(sm, x0, srow, sko);
        stageB_async(smem_u32(sm) + 20480, 0, tid);
        CP_COMMIT();
        gemm_loadA(xa, p0, srow, sko, 1);
        CP_WAIT0();
    }
    __syncthreads();

    for (int kc = 0; kc < 6; kc++) {
        const uint32_t cur = smem_u32(sm + (size_t)(kc & 1) * GBUF);
        #pragma unroll
        for (int s = 0; s < 2; s++) {
            uint32_t ah[2][4], al[2][4];
            #pragma unroll
            for (int mt = 0; mt < 2; mt++) {
                uint32_t aa = cur + abase + mt * 1280 + s * 32;
                ldsm4(ah[mt], aa);
                ldsm4(al[mt], aa + 10240);
            }
            #pragma unroll
            for (int np = 0; np < 4; np++) {
                uint32_t bb = cur + bbase + np * 1280 + s * 32;
                uint32_t bh[4], bl[4];
                ldsm4(bh, bb);
                ldsm4(bl, bb + 10240);
                #pragma unroll
                for (int mt = 0; mt < 2; mt++) {
                    const int t = mt * 8 + np * 2;
                    mma_bf16(acc[t],     ah[mt], bh[0], bh[1]);
                    mma_bf16(acc[t + 1], ah[mt], bh[2], bh[3]);
                    mma_bf16(acc[t],     ah[mt], bl[0], bl[1]);
                    mma_bf16(acc[t + 1], ah[mt], bl[2], bl[3]);
                    mma_bf16(acc[t],     al[mt], bh[0], bh[1]);
                    mma_bf16(acc[t + 1], al[mt], bh[2], bh[3]);
                }
            }
        }
        if (kc < 5) {
            char* nxt = sm + (size_t)((kc + 1) & 1) * GBUF;
            stageB_async(smem_u32(nxt) + 20480, kc + 1, tid);
            CP_COMMIT();
            gemm_cvtstoreA(nxt, xa, srow, sko);
            if (kc < 4) gemm_loadA(xa, p0, srow, sko, kc + 2);
            CP_WAIT0();
        }
        __syncthreads();
    }

    // epilogue: add P gathers, write pfco
    const int g = lane >> 2, c2 = (lane & 3) * 2;
    #pragma unroll
    for (int mt = 0; mt < 2; mt++) {
        #pragma unroll
        for (int r = 0; r < 2; r++) {
            const int p = p0 + mrow + mt * 16 + g + r * 8;
            if (p >= NPTS) continue;
            const int v0 = pv0[p], v1 = pv1[p], v2 = pv2[p];
            const float* P0 = &g_P[(size_t)v0 * 128];
            const float* P1 = &g_P[(size_t)(40000 + v1) * 128];
            const float* P2 = &g_P[(size_t)(60000 + v2) * 128];
            float* dst = &g_pfco[(size_t)p * 128];
            #pragma unroll
            for (int np = 0; np < 4; np++) {
                #pragma unroll
                for (int h = 0; h < 2; h++) {
                    const int t = mt * 8 + np * 2 + h;
                    const int col = ncol + np * 16 + h * 8 + c2;
                    float2 q0 = *(const float2*)(P0 + col);
                    float2 q1 = *(const float2*)(P1 + col);
                    float2 q2 = *(const float2*)(P2 + col);
                    float2 o;
                    o.x = acc[t][r * 2 + 0] + q0.x + q1.x + q2.x;
                    o.y = acc[t][r * 2 + 1] + q0.y + q1.y + q2.y;
                    *(float2*)(dst + col) = o;
                }
            }
        }
    }
}

// ---------------- scales 3..4: 2 warps/voxel gather, att GEMV * pfc_o, max-merge, scatter ----------------
__global__ __launch_bounds__(256) void k_out34v(const float4* __restrict__ pts,
                                                const float* __restrict__ vlc3,
                                                const float* __restrict__ vlc4,
                                                const float* __restrict__ Watt,
                                                const int* __restrict__ vfs3,
                                                const int* __restrict__ vfs4,
                                                float* __restrict__ out) {
    __shared__ float sM[4][32][4];   // per-voxel partial maxima from half=1 warps
    const int lane = threadIdx.x & 31, warp = threadIdx.x >> 5;
    const int vslot = warp >> 1;     // 0..3 voxel within block
    const int half = warp & 1;       // point-parity handled by this warp
    ull wr[12][2];
    {
        const float* W = Watt + lane * 4;
        float4 w0 = *(const float4*)(W + 0 * 128), w1 = *(const float4*)(W + 1 * 128);
        float4 w2 = *(const float4*)(W + 2 * 128), w3 = *(const float4*)(W + 3 * 128);
        float4 w4 = *(const float4*)(W + 4 * 128), w5 = *(const float4*)(W + 5 * 128);
        float4 w6 = *(const float4*)(W + 6 * 128), w7 = *(const float4*)(W + 7 * 128);
        float4 w8 = *(const float4*)(W + 8 * 128), w9 = *(const float4*)(W + 9 * 128);
        float4 w10 = *(const float4*)(W + 10 * 128), w11 = *(const float4*)(W + 11 * 128);
        float4 w12 = *(const float4*)(W + 12 * 128);
        float4 w16 = *(const float4*)(W + 16 * 128), w17 = *(const float4*)(W + 17 * 128);
        float4 L0, L1, L2, R4, R5, R6;
        L0.x = w0.x + w4.x; L0.y = w0.y + w4.y; L0.z = w0.z + w4.z; L0.w = w0.w + w4.w;
        L1.x = w1.x + w5.x; L1.y = w1.y + w5.y; L1.z = w1.z + w5.z; L1.w = w1.w + w5.w;
        L2.x = w2.x + w6.x; L2.y = w2.y + w6.y; L2.z = w2.z + w6.z; L2.w = w2.w + w6.w;
        R4.x = w9.x - L0.x; R4.y = w9.y - L0.y; R4.z = w9.z - L0.z; R4.w = w9.w - L0.w;
        R5.x = w10.x - L1.x; R5.y = w10.y - L1.y; R5.z = w10.z - L1.z; R5.w = w10.w - L1.w;
        R6.x = w11.x - L2.x; R6.y = w11.y - L2.y; R6.z = w11.z - L2.z; R6.w = w11.w - L2.w;
        wr[0][0] = pk2(L0.x, L0.y);  wr[0][1] = pk2(L0.z, L0.w);
        wr[1][0] = pk2(L1.x, L1.y);  wr[1][1] = pk2(L1.z, L1.w);
        wr[2][0] = pk2(L2.x, L2.y);  wr[2][1] = pk2(L2.z, L2.w);
        wr[3][0] = pk2(w3.x, w3.y);  wr[3][1] = pk2(w3.z, w3.w);
        wr[4][0] = pk2(R4.x, R4.y);  wr[4][1] = pk2(R4.z, R4.w);
        wr[5][0] = pk2(R5.x, R5.y);  wr[5][1] = pk2(R5.z, R5.w);
        wr[6][0] = pk2(R6.x, R6.y);  wr[6][1] = pk2(R6.z, R6.w);
        wr[7][0] = pk2(w12.x, w12.y); wr[7][1] = pk2(w12.z, w12.w);
        wr[8][0] = pk2(w7.x, w7.y);  wr[8][1] = pk2(w7.z, w7.w);
        wr[9][0] = pk2(w8.x, w8.y);  wr[9][1] = pk2(w8.z, w8.w);
        wr[10][0] = pk2(w16.x, w16.y); wr[10][1] = pk2(w16.z, w16.w);
        wr[11][0] = pk2(w17.x, w17.y); wr[11][1] = pk2(w17.z, w17.w);
    }
    const int gw = blockIdx.x * 4 + vslot;          // 0..29999
    const int s = (gw >= 20000);
    const int v = s ? gw - 20000 : gw;
    const int soff = s ? 90000 : 70000;
    const int cap = s ? 80 : 48;
    const int pbase = s ? 4000000 : 3040000;
    const float* vlc = s ? vlc4 : vlc3;

    int cnt = g_cur[soff + v];
    if (cnt > cap) cnt = cap;
    const int* lst = &g_plist[pbase + v * cap];

    const float4* s4 = (const float4*)&g_stats[(size_t)(soff + v) * 8];
    float4 sa = s4[0], sb = s4[1];
    float inv = 1.0f / fmaxf(sb.z, 1.0f);
    ull cp4 = dup2(sa.x * inv), cp5 = dup2(sa.y * inv), cp6 = dup2(sa.z * inv), cp7 = dup2(sa.w * inv);
    ull cm0 = dup2(sb.x * inv), cm1 = dup2(sb.y * inv);

    float m0 = FINFO_MIN_F, m1 = FINFO_MIN_F, m2 = FINFO_MIN_F, m3 = FINFO_MIN_F;
    // this warp handles points with index parity == half; 2 in flight
    int j = half;
    for (; j + 2 < cnt; j += 4) {
        int pA = lst[j], pB = lst[j + 2];
        float4 qA = pts[pA], qB = pts[pB];
        float vlxA = vlc[3 * pA], vlyA = vlc[3 * pA + 1];
        float vlxB = vlc[3 * pB], vlyB = vlc[3 * pB + 1];
        ulonglong2 povA = *(const ulonglong2*)&g_pfco[(size_t)pA * 128 + lane * 4];
        ulonglong2 povB = *(const ulonglong2*)&g_pfco[(size_t)pB * 128 + lane * 4];
        {
            ull ca[12] = {dup2(qA.x), dup2(qA.y), dup2(qA.z), dup2(qA.w),
                          cp4, cp5, cp6, cp7, dup2(vlxA), dup2(vlyA), cm0, cm1};
            ull a0 = 0, a1 = 0;
            #pragma unroll
            for (int r = 0; r < 12; r++) { fma2(a0, ca[r], wr[r][0]); fma2(a1, ca[r], wr[r][1]); }
            ull f0 = mul2(a0, povA.x), f1 = mul2(a1, povA.y);
            float x0, x1, x2, x3;
            up2(x0, x1, f0); up2(x2, x3, f1);
            m0 = fmaxf(m0, x0); m1 = fmaxf(m1, x1); m2 = fmaxf(m2, x2); m3 = fmaxf(m3, x3);
        }
        {
            ull ca[12] = {dup2(qB.x), dup2(qB.y), dup2(qB.z), dup2(qB.w),
                          cp4, cp5, cp6, cp7, dup2(vlxB), dup2(vlyB), cm0, cm1};
            ull a0 = 0, a1 = 0;
            #pragma unroll
            for (int r = 0; r < 12; r++) { fma2(a0, ca[r], wr[r][0]); fma2(a1, ca[r], wr[r][1]); }
            ull f0 = mul2(a0, povB.x), f1 = mul2(a1, povB.y);
            float x0, x1, x2, x3;
            up2(x0, x1, f0); up2(x2, x3, f1);
            m0 = fmaxf(m0, x0); m1 = fmaxf(m1, x1); m2 = fmaxf(m2, x2); m3 = fmaxf(m3, x3);
        }
    }
    if (j < cnt) {
        int p = lst[j];
        float4 q = pts[p];
        float vlx = vlc[3 * p], vly = vlc[3 * p + 1];
        ulonglong2 pov = *(const ulonglong2*)&g_pfco[(size_t)p * 128 + lane * 4];
        ull ca[12] = {dup2(q.x), dup2(q.y), dup2(q.z), dup2(q.w),
                      cp4, cp5, cp6, cp7, dup2(vlx), dup2(vly), cm0, cm1};
        ull a0 = 0, a1 = 0;
        #pragma unroll
        for (int r = 0; r < 12; r++) { fma2(a0, ca[r], wr[r][0]); fma2(a1, ca[r], wr[r][1]); }
        ull f0 = mul2(a0, pov.x), f1 = mul2(a1, pov.y);
        float x0, x1, x2, x3;
        up2(x0, x1, f0); up2(x2, x3, f1);
        m0 = fmaxf(m0, x0); m1 = fmaxf(m1, x1); m2 = fmaxf(m2, x2); m3 = fmaxf(m3, x3);
    }
    // merge: half=1 writes partial maxima; half=0 combines and scatters
    if (half == 1) {
        sM[vslot][lane][0] = m0; sM[vslot][lane][1] = m1;
        sM[vslot][lane][2] = m2; sM[vslot][lane][3] = m3;
    }
    __syncthreads();
    if (half == 0) {
        m0 = fmaxf(m0, sM[vslot][lane][0]);
        m1 = fmaxf(m1, sM[vslot][lane][1]);
        m2 = fmaxf(m2, sM[vslot][lane][2]);
        m3 = fmaxf(m3, sM[vslot][lane][3]);
        const int* vr = s ? &vfs4[3 * v] : &vfs3[3 * v];
        int b_ = vr[0], y = vr[1], x = vr[2];
        const int HW = s ? 8836 : 35344;
        const int Wd = s ? 94 : 188;
        float* ob = s ? (out + (size_t)2 * 128 * 35344) : out;
        size_t base = ((size_t)b_ * 128 + lane * 4) * (size_t)HW + (size_t)y * Wd + x;
        ob[base] = m0;
        ob[base + HW] = m1;
        ob[base + 2 * (size_t)HW] = m2;
        ob[base + 3 * (size_t)HW] = m3;
    }
}

// ---------------- host ----------------
extern "C" void kernel_launch(void* const* d_in, const int* in_sizes, int n_in,
                              void* d_out, int out_size) {
    const float* points = nullptr;
    Ptrs io = {};
    const int* vfs[5] = {};
    const float *Wp = nullptr, *Wa = nullptr, *Wo = nullptr, *Watt = nullptr;
    int nv = 0, np = 0, n60 = 0, n30 = 0;
    for (int i = 0; i < n_in; i++) {
        switch (in_sizes[i]) {
            case 800000: points = (const float*)d_in[i]; break;
            case 600000: if (nv < 5) io.vlc[nv++] = (const float*)d_in[i]; break;
            case 200000: if (np < 5) io.pv[np++] = (const int*)d_in[i]; break;
            case 120000: vfs[0] = (const int*)d_in[i]; break;
            case 60000:  vfs[n60 ? 3 : 1] = (const int*)d_in[i]; n60++; break;
            case 30000:  vfs[n30 ? 4 : 2] = (const int*)d_in[i]; n30++; break;
            case 576:    Wp = (const float*)d_in[i]; break;
            case 1152:   Wa = (const float*)d_in[i]; break;
            case 49152:  Wo = (const float*)d_in[i]; break;
            case 2304:   Watt = (const float*)d_in[i]; break;
            default: break;
        }
    }
    float* out = (float*)d_out;

    void* p_stats = nullptr;
    void* p_cur = nullptr;
    cudaGetSymbolAddress(&p_stats, g_stats);
    cudaGetSymbolAddress(&p_cur, g_cur);
    cudaFuncSetAttribute(k_gemm, cudaFuncAttributeMaxDynamicSharedMemorySize, 2 * GBUF);

    cudaMemsetAsync(d_out, 0, (size_t)out_size * sizeof(float));
    cudaMemsetAsync(p_stats, 0, 100000ull * 8 * sizeof(float));
    cudaMemsetAsync(p_cur, 0, 100000ull * sizeof(int));
    k_wcvt<<<96, 256>>>(Wo);
    k_statsfill<<<(NPTS + 255) / 256, 256>>>((const float4*)points, io);
    k_avfe<<<(NPTS + 255) / 256, 256>>>((const float4*)points, io, Wp, Wa);
    k_pvoxm<<<1095, 256>>>(Wo);
    k_gemm<<<(NPTS + 127) / 128, 256, 2 * GBUF>>>(io.pv[0], io.pv[1], io.pv[2]);
    k_out34v<<<7500, 256>>>((const float4*)points, io.vlc[3], io.vlc[4], Watt,
                            vfs[3], vfs[4], out);
}

// round 15
// speedup vs baseline: 1.1912x; 1.1912x over previous
#include <cuda_runtime.h>
#include <cuda_bf16.h>
#include <stdint.h>

#define NPTS 200000
#define FINFO_MIN_F (-3.4028234663852886e38f)

typedef unsigned long long ull;

// ---------------- scratch (device globals; no allocs allowed) ----------------
__device__ float g_stats[100000 * 8];            // per (scale,voxel): sums x,y,z,w, vlx,vly, cnt, pad
__device__ int   g_cur[100000];                  // per (scale,voxel) point counter
__device__ int   g_plist[4800000];               // fixed-capacity point lists per (scale,voxel)
__device__ float g_P[70000 * 128];               // per-voxel vf @ W_o slice
__device__ float g_final[(size_t)200064 * 192];  // final0|final1|final2 per point (padded)
__device__ float g_pfco[(size_t)NPTS * 128];     // feat @ W_avfeo_point
__device__ uint4 g_Bcvt[7680];                   // Wo(final rows) as bf16 hi/lo smem images, 6 chunks

// ---------------- f32x2 / RED helpers ----------------
__device__ __forceinline__ ull dup2(float x) {
    ull r; asm("mov.b64 %0,{%1,%1};" : "=l"(r) : "f"(x)); return r;
}
__device__ __forceinline__ ull pk2(float x, float y) {
    ull r; asm("mov.b64 %0,{%1,%2};" : "=l"(r) : "f"(x), "f"(y)); return r;
}
__device__ __forceinline__ void fma2(ull& d, ull a, ull b) {
    asm("fma.rn.f32x2 %0,%1,%2,%0;" : "+l"(d) : "l"(a), "l"(b));
}
__device__ __forceinline__ ull mul2(ull a, ull b) {
    ull d; asm("mul.rn.f32x2 %0,%1,%2;" : "=l"(d) : "l"(a), "l"(b)); return d;
}
__device__ __forceinline__ void up2(float& x, float& y, ull a) {
    asm("mov.b64 {%0,%1},%2;" : "=f"(x), "=f"(y) : "l"(a));
}
__device__ __forceinline__ void redadd4(float* p, float a, float b, float c, float d) {
    asm volatile("red.global.add.v4.f32 [%0], {%1,%2,%3,%4};"
                 :: "l"(__cvta_generic_to_global(p)), "f"(a), "f"(b), "f"(c), "f"(d) : "memory");
}

// ---------------- mma / cp.async helpers ----------------
__device__ __forceinline__ uint32_t smem_u32(const void* p) {
    uint32_t a;
    asm("{ .reg .u64 t; cvta.to.shared.u64 t, %1; cvt.u32.u64 %0, t; }" : "=r"(a) : "l"(p));
    return a;
}
__device__ __forceinline__ void ldsm4(uint32_t* r, uint32_t addr) {
    asm volatile("ldmatrix.sync.aligned.m8n8.x4.shared.b16 {%0,%1,%2,%3}, [%4];"
                 : "=r"(r[0]), "=r"(r[1]), "=r"(r[2]), "=r"(r[3]) : "r"(addr));
}
__device__ __forceinline__ void mma_bf16(float* d, const uint32_t* a, uint32_t b0, uint32_t b1) {
    asm volatile(
        "mma.sync.aligned.m16n8k16.row.col.f32.bf16.bf16.f32 "
        "{%0,%1,%2,%3}, {%4,%5,%6,%7}, {%8,%9}, {%0,%1,%2,%3};"
        : "+f"(d[0]), "+f"(d[1]), "+f"(d[2]), "+f"(d[3])
        : "r"(a[0]), "r"(a[1]), "r"(a[2]), "r"(a[3]), "r"(b0), "r"(b1));
}
__device__ __forceinline__ void cpasync16(uint32_t smaddr, const void* g) {
    asm volatile("cp.async.ca.shared.global [%0], [%1], 16;"
                 :: "r"(smaddr), "l"(g) : "memory");
}
#define CP_COMMIT() asm volatile("cp.async.commit_group;" ::: "memory")
#define CP_WAIT0()  asm volatile("cp.async.wait_group 0;" ::: "memory")

__device__ __forceinline__ void cvt8(const float* x, uint4& hi, uint4& lo) {
    unsigned h[4], l[4];
    #pragma unroll
    for (int i = 0; i < 4; i++) {
        __nv_bfloat162 hb = __floats2bfloat162_rn(x[2 * i], x[2 * i + 1]);
        float f0 = __bfloat162float(hb.x), f1 = __bfloat162float(hb.y);
        __nv_bfloat162 lb = __floats2bfloat162_rn(x[2 * i] - f0, x[2 * i + 1] - f1);
        h[i] = *(unsigned*)&hb;
        l[i] = *(unsigned*)&lb;
    }
    hi.x = h[0]; hi.y = h[1]; hi.z = h[2]; hi.w = h[3];
    lo.x = l[0]; lo.y = l[1]; lo.z = l[2]; lo.w = l[3];
}

struct Ptrs {
    const float* vlc[5];
    const int*   pv[5];
};

// per-scale layout: soff {0,40000,60000,70000,90000}, cap {32,48,80,48,80},
// pbase {0,1280000,2240000,3040000,4000000}

// ---------------- per-voxel sums + point-list fill, all 5 scales ----------------
__global__ __launch_bounds__(256) void k_statsfill(const float4* __restrict__ pts, Ptrs io) {
    int p = blockIdx.x * 256 + threadIdx.x;
    if (p >= NPTS) return;
    float4 q = pts[p];
    const int soffs[5]  = {0, 40000, 60000, 70000, 90000};
    const int caps[5]   = {32, 48, 80, 48, 80};
    const int pbases[5] = {0, 1280000, 2240000, 3040000, 4000000};
    #pragma unroll
    for (int i = 0; i < 5; i++) {
        int v = io.pv[i][p];
        float vx = io.vlc[i][3 * p], vy = io.vlc[i][3 * p + 1];
        float* s = &g_stats[(size_t)(soffs[i] + v) * 8];
        redadd4(s, q.x, q.y, q.z, q.w);
        redadd4(s + 4, vx, vy, 1.0f, 0.0f);
        int slot = atomicAdd(&g_cur[soffs[i] + v], 1);
        if (slot < caps[i]) g_plist[pbases[i] + v * caps[i] + slot] = p;
    }
}

// ---------------- Wo(final rows) -> bf16 hi/lo smem image, once ----------------
__global__ __launch_bounds__(256) void k_wcvt(const float* __restrict__ Wo) {
    int idx = blockIdx.x * 256 + threadIdx.x;
    if (idx >= 192 * 128) return;
    int kk = idx >> 7, n = idx & 127;
    int kc = kk >> 5, ko = kk & 31;
    int r = ((kk >> 6) << 7) + (kk & 63);     // rows {0..63,128..191,256..319}
    float v = Wo[(size_t)r * 128 + n];
    __nv_bfloat16 hb = __float2bfloat16_rn(v);
    __nv_bfloat16 lb = __float2bfloat16_rn(v - __bfloat162float(hb));
    char* base = (char*)g_Bcvt + kc * 20480 + n * 80 + ko * 2;
    *(__nv_bfloat16*)base = hb;
    *(__nv_bfloat16*)(base + 10240) = lb;
}

// ---------------- scales 0..2: folded-basis dual GEMV + product -> g_final ----------------
__global__ __launch_bounds__(256) void k_avfe(const float4* __restrict__ pts, Ptrs io,
                                              const float* __restrict__ Wp,
                                              const float* __restrict__ Wa) {
    __shared__ float sP[9 * 64];
    __shared__ float sA[12 * 64];
    const int tid = threadIdx.x;
    if (tid < 64) {
        const int c = tid;
        float w0 = Wp[c], w1 = Wp[64 + c], w2 = Wp[128 + c], w3 = Wp[192 + c];
        float w4 = Wp[256 + c], w5 = Wp[320 + c], w6 = Wp[384 + c], w7 = Wp[448 + c], w8 = Wp[512 + c];
        sP[0 * 64 + c] = w0 + w4; sP[1 * 64 + c] = w1 + w5; sP[2 * 64 + c] = w2 + w6;
        sP[3 * 64 + c] = w3;
        sP[4 * 64 + c] = -w4; sP[5 * 64 + c] = -w5; sP[6 * 64 + c] = -w6;
        sP[7 * 64 + c] = w7; sP[8 * 64 + c] = w8;
        float a0 = Wa[c], a1 = Wa[64 + c], a2 = Wa[128 + c], a3 = Wa[192 + c];
        float a4 = Wa[256 + c], a5 = Wa[320 + c], a6 = Wa[384 + c];
        float a7 = Wa[448 + c], a8 = Wa[512 + c];
        float a9 = Wa[576 + c], a10 = Wa[640 + c], a11 = Wa[704 + c], a12 = Wa[768 + c];
        float a16 = Wa[1024 + c], a17 = Wa[1088 + c];
        float L0 = a0 + a4, L1 = a1 + a5, L2 = a2 + a6;
        sA[0 * 64 + c] = L0; sA[1 * 64 + c] = L1; sA[2 * 64 + c] = L2; sA[3 * 64 + c] = a3;
        sA[4 * 64 + c] = a9 - L0; sA[5 * 64 + c] = a10 - L1; sA[6 * 64 + c] = a11 - L2;
        sA[7 * 64 + c] = a12;
        sA[8 * 64 + c] = a7; sA[9 * 64 + c] = a8;
        sA[10 * 64 + c] = a16; sA[11 * 64 + c] = a17;
    }
    __syncthreads();
    const int p = blockIdx.x * 256 + tid;
    if (p >= NPTS) return;
    float4 q = pts[p];
    ull cqx = dup2(q.x), cqy = dup2(q.y), cqz = dup2(q.z), cqw = dup2(q.w);
    #pragma unroll
    for (int i = 0; i < 3; i++) {
        const int soff = (i == 0) ? 0 : ((i == 1) ? 40000 : 60000);
        int v = io.pv[i][p];
        float vlx = io.vlc[i][3 * p], vly = io.vlc[i][3 * p + 1];
        const float4* s4 = (const float4*)&g_stats[(size_t)(soff + v) * 8];
        float4 sa = s4[0], sb = s4[1];
        float inv = 1.0f / fmaxf(sb.z, 1.0f);
        ull cp4 = dup2(sa.x * inv), cp5 = dup2(sa.y * inv), cp6 = dup2(sa.z * inv), cp7 = dup2(sa.w * inv);
        ull cv0 = dup2(vlx), cv1 = dup2(vly);
        ull cm0 = dup2(sb.x * inv), cm1 = dup2(sb.y * inv);
        ull cp[9]  = {cqx, cqy, cqz, cqw, cp4, cp5, cp6, cv0, cv1};
        ull ca[12] = {cqx, cqy, cqz, cqw, cp4, cp5, cp6, cp7, cv0, cv1, cm0, cm1};
        float* fout = &g_final[(size_t)p * 192 + i * 64];
        #pragma unroll 2
        for (int c = 0; c < 64; c += 4) {
            ull p0 = 0, p1 = 0, a0 = 0, a1 = 0;
            #pragma unroll
            for (int r = 0; r < 9; r++) {
                ulonglong2 w = *(const ulonglong2*)&sP[r * 64 + c];
                fma2(p0, cp[r], w.x); fma2(p1, cp[r], w.y);
            }
            #pragma unroll
            for (int r = 0; r < 12; r++) {
                ulonglong2 w = *(const ulonglong2*)&sA[r * 64 + c];
                fma2(a0, ca[r], w.x); fma2(a1, ca[r], w.y);
            }
            ulonglong2 fo; fo.x = mul2(a0, p0); fo.y = mul2(a1, p1);
            *(ulonglong2*)&fout[c] = fo;
        }
    }
}

// ---------------- fused gather-max + GEMM: P = max_pts(final) @ W_o[vf-rows] ----------------
__global__ __launch_bounds__(256) void k_pvoxm(const float* __restrict__ Wo) {
    __shared__ float sA[64 * 68];
    const int b = blockIdx.x, tid = threadIdx.x;
    int voff, V, wrow, vb, cap, pbase, scoff;
    if (b < 625)      { voff = 0;     V = 40000; wrow = 64;  vb = b * 64;         cap = 32; pbase = 0;       scoff = 0; }
    else if (b < 938) { voff = 40000; V = 20000; wrow = 192; vb = (b - 625) * 64; cap = 48; pbase = 1280000; scoff = 64; }
    else              { voff = 60000; V = 10000; wrow = 320; vb = (b - 938) * 64; cap = 80; pbase = 2240000; scoff = 128; }
    {
        const int vl = tid >> 2, sub = tid & 3;
        const int v = vb + vl;
        float mx[16];
        #pragma unroll
        for (int c = 0; c < 16; c++) mx[c] = FINFO_MIN_F;
        if (v < V) {
            int cnt = g_cur[voff + v];
            if (cnt > cap) cnt = cap;
            const int* lst = &g_plist[pbase + v * cap];
            const int chb = sub * 16;
            int j = 0;
            for (; j + 2 <= cnt; j += 2) {
                int pA = lst[j], pB = lst[j + 1];
                const float4* fA = (const float4*)&g_final[(size_t)pA * 192 + scoff + chb];
                const float4* fB = (const float4*)&g_final[(size_t)pB * 192 + scoff + chb];
                float4 a0 = fA[0], a1 = fA[1], a2 = fA[2], a3 = fA[3];
                float4 b0 = fB[0], b1 = fB[1], b2 = fB[2], b3 = fB[3];
                mx[0] = fmaxf(mx[0], fmaxf(a0.x, b0.x)); mx[1] = fmaxf(mx[1], fmaxf(a0.y, b0.y));
                mx[2] = fmaxf(mx[2], fmaxf(a0.z, b0.z)); mx[3] = fmaxf(mx[3], fmaxf(a0.w, b0.w));
                mx[4] = fmaxf(mx[4], fmaxf(a1.x, b1.x)); mx[5] = fmaxf(mx[5], fmaxf(a1.y, b1.y));
                mx[6] = fmaxf(mx[6], fmaxf(a1.z, b1.z)); mx[7] = fmaxf(mx[7], fmaxf(a1.w, b1.w));
                mx[8] = fmaxf(mx[8], fmaxf(a2.x, b2.x)); mx[9] = fmaxf(mx[9], fmaxf(a2.y, b2.y));
                mx[10] = fmaxf(mx[10], fmaxf(a2.z, b2.z)); mx[11] = fmaxf(mx[11], fmaxf(a2.w, b2.w));
                mx[12] = fmaxf(mx[12], fmaxf(a3.x, b3.x)); mx[13] = fmaxf(mx[13], fmaxf(a3.y, b3.y));
                mx[14] = fmaxf(mx[14], fmaxf(a3.z, b3.z)); mx[15] = fmaxf(mx[15], fmaxf(a3.w, b3.w));
            }
            if (j < cnt) {
                int p = lst[j];
                const float4* f = (const float4*)&g_final[(size_t)p * 192 + scoff + chb];
                float4 x0 = f[0], x1 = f[1], x2 = f[2], x3 = f[3];
                mx[0] = fmaxf(mx[0], x0.x); mx[1] = fmaxf(mx[1], x0.y);
                mx[2] = fmaxf(mx[2], x0.z); mx[3] = fmaxf(mx[3], x0.w);
                mx[4] = fmaxf(mx[4], x1.x); mx[5] = fmaxf(mx[5], x1.y);
                mx[6] = fmaxf(mx[6], x1.z); mx[7] = fmaxf(mx[7], x1.w);
                mx[8] = fmaxf(mx[8], x2.x); mx[9] = fmaxf(mx[9], x2.y);
                mx[10] = fmaxf(mx[10], x2.z); mx[11] = fmaxf(mx[11], x2.w);
                mx[12] = fmaxf(mx[12], x3.x); mx[13] = fmaxf(mx[13], x3.y);
                mx[14] = fmaxf(mx[14], x3.z); mx[15] = fmaxf(mx[15], x3.w);
            }
        }
        const int chb = sub * 16;
        #pragma unroll
        for (int c = 0; c < 16; c++) sA[(chb + c) * 68 + vl] = mx[c];
    }
    __syncthreads();
    const int pg = tid >> 4, cg = tid & 15;
    const float* Wb = Wo + (size_t)wrow * 128 + cg * 8;
    ull acc[4][4] = {};
    #pragma unroll 8
    for (int k = 0; k < 64; k++) {
        float4 av = *(const float4*)&sA[k * 68 + pg * 4];
        ull a0 = dup2(av.x), a1 = dup2(av.y), a2 = dup2(av.z), a3 = dup2(av.w);
        const float* br = Wb + (size_t)k * 128;
        ulonglong2 b0 = *(const ulonglong2*)br;
        ulonglong2 b1 = *(const ulonglong2*)(br + 4);
        fma2(acc[0][0], a0, b0.x); fma2(acc[0][1], a0, b0.y); fma2(acc[0][2], a0, b1.x); fma2(acc[0][3], a0, b1.y);
        fma2(acc[1][0], a1, b0.x); fma2(acc[1][1], a1, b0.y); fma2(acc[1][2], a1, b1.x); fma2(acc[1][3], a1, b1.y);
        fma2(acc[2][0], a2, b0.x); fma2(acc[2][1], a2, b0.y); fma2(acc[2][2], a2, b1.x); fma2(acc[2][3], a2, b1.y);
        fma2(acc[3][0], a3, b0.x); fma2(acc[3][1], a3, b0.y); fma2(acc[3][2], a3, b1.x); fma2(acc[3][3], a3, b1.y);
    }
    #pragma unroll
    for (int m = 0; m < 4; m++) {
        int v = vb + pg * 4 + m;
        if (v < V) {
            float* dst = &g_P[(size_t)(voff + v) * 128 + cg * 8];
            ulonglong2 o0; o0.x = acc[m][0]; o0.y = acc[m][1];
            ulonglong2 o1; o1.x = acc[m][2]; o1.y = acc[m][3];
            *(ulonglong2*)dst = o0;
            *(ulonglong2*)(dst + 4) = o1;
        }
    }
}

// ---------------- main GEMM: mma.sync bf16 3-way split, K=192, 2x2 warp tile ----------------
// per buffer (40960 B): A_hi[128][40 bf16] @0, A_lo @10240, B_hi @20480, B_lo @30720
#define GBUF 40960

__device__ __forceinline__ void gemm_cvtstoreA(char* buf, const float* x, int srow, int sko) {
    uint4 h0, l0, h1, l1;
    cvt8(x, h0, l0); cvt8(x + 8, h1, l1);
    char* pa = buf + srow * 80 + sko * 2;
    *(uint4*)pa = h0;
    *(uint4*)(pa + 16) = h1;
    *(uint4*)(pa + 10240) = l0;
    *(uint4*)(pa + 10240 + 16) = l1;
}
__device__ __forceinline__ void gemm_loadA(float* x, int p0, int srow, int sko, int kc) {
    const float* src = &g_final[(size_t)(p0 + srow) * 192 + kc * 32 + sko];
    *(float4*)(x) = ((const float4*)src)[0];
    *(float4*)(x + 4) = ((const float4*)src)[1];
    *(float4*)(x + 8) = ((const float4*)src)[2];
    *(float4*)(x + 12) = ((const float4*)src)[3];
}
__device__ __forceinline__ void stageB_async(uint32_t dst, int kc, int tid) {
    const uint4* src = g_Bcvt + kc * 1280 + tid;
    #pragma unroll
    for (int i = 0; i < 5; i++)
        cpasync16(dst + (uint32_t)(tid + i * 256) * 16, src + i * 256);
}

__global__ __launch_bounds__(256, 2) void k_gemm(const int* __restrict__ pv0,
                                                 const int* __restrict__ pv1,
                                                 const int* __restrict__ pv2) {
    extern __shared__ __align__(16) char sm[];
    const int tid = threadIdx.x, lane = tid & 31, wid = tid >> 5;
    const int p0 = blockIdx.x * 128;
    const int mrow = (wid & 3) * 32;
    const int ncol = (wid >> 2) * 64;

    float acc[16][4] = {};
    const uint32_t abase = (uint32_t)((mrow + (lane & 15)) * 80 + ((lane >> 4) << 4));
    const uint32_t bbase = (uint32_t)(20480 + (ncol + (lane & 7) + ((lane >> 4) << 3)) * 80
                                      + ((lane & 8) << 1));
    const int srow = tid >> 1, sko = (tid & 1) * 16;

    float xa[16];
    {   // prologue: stage kc=0 (A cvt + B async), preload A(kc=1)
        float x0[16];
        gemm_loadA(x0, p0, srow, sko, 0);
        gemm_cvtstoreA(sm, x0, srow, sko);
        stageB_async(smem_u32(sm) + 20480, 0, tid);
        CP_COMMIT();
        gemm_loadA(xa, p0, srow, sko, 1);
        CP_WAIT0();
    }
    __syncthreads();

    for (int kc = 0; kc < 6; kc++) {
        const uint32_t cur = smem_u32(sm + (size_t)(kc & 1) * GBUF);
        #pragma unroll
        for (int s = 0; s < 2; s++) {
            uint32_t ah[2][4], al[2][4];
            #pragma unroll
            for (int mt = 0; mt < 2; mt++) {
                uint32_t aa = cur + abase + mt * 1280 + s * 32;
                ldsm4(ah[mt], aa);
                ldsm4(al[mt], aa + 10240);
            }
            #pragma unroll
            for (int np = 0; np < 4; np++) {
                uint32_t bb = cur + bbase + np * 1280 + s * 32;
                uint32_t bh[4], bl[4];
                ldsm4(bh, bb);
                ldsm4(bl, bb + 10240);
                #pragma unroll
                for (int mt = 0; mt < 2; mt++) {
                    const int t = mt * 8 + np * 2;
                    mma_bf16(acc[t],     ah[mt], bh[0], bh[1]);
                    mma_bf16(acc[t + 1], ah[mt], bh[2], bh[3]);
                    mma_bf16(acc[t],     ah[mt], bl[0], bl[1]);
                    mma_bf16(acc[t + 1], ah[mt], bl[2], bl[3]);
                    mma_bf16(acc[t],     al[mt], bh[0], bh[1]);
                    mma_bf16(acc[t + 1], al[mt], bh[2], bh[3]);
                }
            }
        }
        if (kc < 5) {
            char* nxt = sm + (size_t)((kc + 1) & 1) * GBUF;
            stageB_async(smem_u32(nxt) + 20480, kc + 1, tid);
            CP_COMMIT();
            gemm_cvtstoreA(nxt, xa, srow, sko);
            if (kc < 4) gemm_loadA(xa, p0, srow, sko, kc + 2);
            CP_WAIT0();
        }
        __syncthreads();
    }

    // epilogue: add P gathers, write pfco
    const int g = lane >> 2, c2 = (lane & 3) * 2;
    #pragma unroll
    for (int mt = 0; mt < 2; mt++) {
        #pragma unroll
        for (int r = 0; r < 2; r++) {
            const int p = p0 + mrow + mt * 16 + g + r * 8;
            if (p >= NPTS) continue;
            const int v0 = pv0[p], v1 = pv1[p], v2 = pv2[p];
            const float* P0 = &g_P[(size_t)v0 * 128];
            const float* P1 = &g_P[(size_t)(40000 + v1) * 128];
            const float* P2 = &g_P[(size_t)(60000 + v2) * 128];
            float* dst = &g_pfco[(size_t)p * 128];
            #pragma unroll
            for (int np = 0; np < 4; np++) {
                #pragma unroll
                for (int h = 0; h < 2; h++) {
                    const int t = mt * 8 + np * 2 + h;
                    const int col = ncol + np * 16 + h * 8 + c2;
                    float2 q0 = *(const float2*)(P0 + col);
                    float2 q1 = *(const float2*)(P1 + col);
                    float2 q2 = *(const float2*)(P2 + col);
                    float2 o;
                    o.x = acc[t][r * 2 + 0] + q0.x + q1.x + q2.x;
                    o.y = acc[t][r * 2 + 1] + q0.y + q1.y + q2.y;
                    *(float2*)(dst + col) = o;
                }
            }
        }
    }
}

// ---------------- scales 3..4: voxel-parallel gather, hoisted GEMV * pfc_o, max, scatter ----------------
__global__ __launch_bounds__(256) void k_out34v(const float4* __restrict__ pts,
                                                const float* __restrict__ vlc3,
                                                const float* __restrict__ vlc4,
                                                const float* __restrict__ Watt,
                                                const int* __restrict__ vfs3,
                                                const int* __restrict__ vfs4,
                                                float* __restrict__ out) {
    const int lane = threadIdx.x & 31, warp = threadIdx.x >> 5;
    // per-point weight rows: q.xyzw (L0,L1,L2,w3) and vl.xy (w7,w8)
    ull wq[4][2], wv[2][2];
    // voxel-constant rows: pm0..3 (R4,R5,R6,w12), vm0..1 (w16,w17)
    ull wm[6][2];
    {
        const float* W = Watt + lane * 4;
        float4 w0 = *(const float4*)(W + 0 * 128), w1 = *(const float4*)(W + 1 * 128);
        float4 w2 = *(const float4*)(W + 2 * 128), w3 = *(const float4*)(W + 3 * 128);
        float4 w4 = *(const float4*)(W + 4 * 128), w5 = *(const float4*)(W + 5 * 128);
        float4 w6 = *(const float4*)(W + 6 * 128), w7 = *(const float4*)(W + 7 * 128);
        float4 w8 = *(const float4*)(W + 8 * 128), w9 = *(const float4*)(W + 9 * 128);
        float4 w10 = *(const float4*)(W + 10 * 128), w11 = *(const float4*)(W + 11 * 128);
        float4 w12 = *(const float4*)(W + 12 * 128);
        float4 w16 = *(const float4*)(W + 16 * 128), w17 = *(const float4*)(W + 17 * 128);
        float4 L0, L1, L2, R4, R5, R6;
        L0.x = w0.x + w4.x; L0.y = w0.y + w4.y; L0.z = w0.z + w4.z; L0.w = w0.w + w4.w;
        L1.x = w1.x + w5.x; L1.y = w1.y + w5.y; L1.z = w1.z + w5.z; L1.w = w1.w + w5.w;
        L2.x = w2.x + w6.x; L2.y = w2.y + w6.y; L2.z = w2.z + w6.z; L2.w = w2.w + w6.w;
        R4.x = w9.x - L0.x; R4.y = w9.y - L0.y; R4.z = w9.z - L0.z; R4.w = w9.w - L0.w;
        R5.x = w10.x - L1.x; R5.y = w10.y - L1.y; R5.z = w10.z - L1.z; R5.w = w10.w - L1.w;
        R6.x = w11.x - L2.x; R6.y = w11.y - L2.y; R6.z = w11.z - L2.z; R6.w = w11.w - L2.w;
        wq[0][0] = pk2(L0.x, L0.y);  wq[0][1] = pk2(L0.z, L0.w);
        wq[1][0] = pk2(L1.x, L1.y);  wq[1][1] = pk2(L1.z, L1.w);
        wq[2][0] = pk2(L2.x, L2.y);  wq[2][1] = pk2(L2.z, L2.w);
        wq[3][0] = pk2(w3.x, w3.y);  wq[3][1] = pk2(w3.z, w3.w);
        wm[0][0] = pk2(R4.x, R4.y);  wm[0][1] = pk2(R4.z, R4.w);
        wm[1][0] = pk2(R5.x, R5.y);  wm[1][1] = pk2(R5.z, R5.w);
        wm[2][0] = pk2(R6.x, R6.y);  wm[2][1] = pk2(R6.z, R6.w);
        wm[3][0] = pk2(w12.x, w12.y); wm[3][1] = pk2(w12.z, w12.w);
        wv[0][0] = pk2(w7.x, w7.y);  wv[0][1] = pk2(w7.z, w7.w);
        wv[1][0] = pk2(w8.x, w8.y);  wv[1][1] = pk2(w8.z, w8.w);
        wm[4][0] = pk2(w16.x, w16.y); wm[4][1] = pk2(w16.z, w16.w);
        wm[5][0] = pk2(w17.x, w17.y); wm[5][1] = pk2(w17.z, w17.w);
    }
    const int gw = blockIdx.x * 8 + warp;
    const int s = (gw >= 20000);
    const int v = s ? gw - 20000 : gw;
    const int soff = s ? 90000 : 70000;
    const int cap = s ? 80 : 48;
    const int pbase = s ? 4000000 : 3040000;
    const float* vlc = s ? vlc4 : vlc3;

    int cnt = g_cur[soff + v];
    if (cnt > cap) cnt = cap;
    const int* lst = &g_plist[pbase + v * cap];

    const float4* s4 = (const float4*)&g_stats[(size_t)(soff + v) * 8];
    float4 sa = s4[0], sb = s4[1];
    float inv = 1.0f / fmaxf(sb.z, 1.0f);
    // hoist voxel-constant partial GEMV: base = sum over pm/vm rows
    ull base0 = 0, base1 = 0;
    {
        ull cmv[6] = {dup2(sa.x * inv), dup2(sa.y * inv), dup2(sa.z * inv), dup2(sa.w * inv),
                      dup2(sb.x * inv), dup2(sb.y * inv)};
        #pragma unroll
        for (int r = 0; r < 6; r++) { fma2(base0, cmv[r], wm[r][0]); fma2(base1, cmv[r], wm[r][1]); }
    }

    float m0 = FINFO_MIN_F, m1 = FINFO_MIN_F, m2 = FINFO_MIN_F, m3 = FINFO_MIN_F;
    int j = 0;
    for (; j + 2 <= cnt; j += 2) {
        int pA = lst[j], pB = lst[j + 1];
        float4 qA = pts[pA], qB = pts[pB];
        float vlxA = vlc[3 * pA], vlyA = vlc[3 * pA + 1];
        float vlxB = vlc[3 * pB], vlyB = vlc[3 * pB + 1];
        ulonglong2 povA = *(const ulonglong2*)&g_pfco[(size_t)pA * 128 + lane * 4];
        ulonglong2 povB = *(const ulonglong2*)&g_pfco[(size_t)pB * 128 + lane * 4];
        {
            ull ca[6] = {dup2(qA.x), dup2(qA.y), dup2(qA.z), dup2(qA.w), dup2(vlxA), dup2(vlyA)};
            ull a0 = base0, a1 = base1;
            #pragma unroll
            for (int r = 0; r < 4; r++) { fma2(a0, ca[r], wq[r][0]); fma2(a1, ca[r], wq[r][1]); }
            fma2(a0, ca[4], wv[0][0]); fma2(a1, ca[4], wv[0][1]);
            fma2(a0, ca[5], wv[1][0]); fma2(a1, ca[5], wv[1][1]);
            ull f0 = mul2(a0, povA.x), f1 = mul2(a1, povA.y);
            float x0, x1, x2, x3;
            up2(x0, x1, f0); up2(x2, x3, f1);
            m0 = fmaxf(m0, x0); m1 = fmaxf(m1, x1); m2 = fmaxf(m2, x2); m3 = fmaxf(m3, x3);
        }
        {
            ull ca[6] = {dup2(qB.x), dup2(qB.y), dup2(qB.z), dup2(qB.w), dup2(vlxB), dup2(vlyB)};
            ull a0 = base0, a1 = base1;
            #pragma unroll
            for (int r = 0; r < 4; r++) { fma2(a0, ca[r], wq[r][0]); fma2(a1, ca[r], wq[r][1]); }
            fma2(a0, ca[4], wv[0][0]); fma2(a1, ca[4], wv[0][1]);
            fma2(a0, ca[5], wv[1][0]); fma2(a1, ca[5], wv[1][1]);
            ull f0 = mul2(a0, povB.x), f1 = mul2(a1, povB.y);
            float x0, x1, x2, x3;
            up2(x0, x1, f0); up2(x2, x3, f1);
            m0 = fmaxf(m0, x0); m1 = fmaxf(m1, x1); m2 = fmaxf(m2, x2); m3 = fmaxf(m3, x3);
        }
    }
    if (j < cnt) {
        int p = lst[j];
        float4 q = pts[p];
        float vlx = vlc[3 * p], vly = vlc[3 * p + 1];
        ulonglong2 pov = *(const ulonglong2*)&g_pfco[(size_t)p * 128 + lane * 4];
        ull ca[6] = {dup2(q.x), dup2(q.y), dup2(q.z), dup2(q.w), dup2(vlx), dup2(vly)};
        ull a0 = base0, a1 = base1;
        #pragma unroll
        for (int r = 0; r < 4; r++) { fma2(a0, ca[r], wq[r][0]); fma2(a1, ca[r], wq[r][1]); }
        fma2(a0, ca[4], wv[0][0]); fma2(a1, ca[4], wv[0][1]);
        fma2(a0, ca[5], wv[1][0]); fma2(a1, ca[5], wv[1][1]);
        ull f0 = mul2(a0, pov.x), f1 = mul2(a1, pov.y);
        float x0, x1, x2, x3;
        up2(x0, x1, f0); up2(x2, x3, f1);
        m0 = fmaxf(m0, x0); m1 = fmaxf(m1, x1); m2 = fmaxf(m2, x2); m3 = fmaxf(m3, x3);
    }
    const int* vr = s ? &vfs4[3 * v] : &vfs3[3 * v];
    int b_ = vr[0], y = vr[1], x = vr[2];
    const int HW = s ? 8836 : 35344;
    const int Wd = s ? 94 : 188;
    float* ob = s ? (out + (size_t)2 * 128 * 35344) : out;
    size_t base = ((size_t)b_ * 128 + lane * 4) * (size_t)HW + (size_t)y * Wd + x;
    ob[base] = m0;
    ob[base + HW] = m1;
    ob[base + 2 * (size_t)HW] = m2;
    ob[base + 3 * (size_t)HW] = m3;
}

// ---------------- host ----------------
extern "C" void kernel_launch(void* const* d_in, const int* in_sizes, int n_in,
                              void* d_out, int out_size) {
    const float* points = nullptr;
    Ptrs io = {};
    const int* vfs[5] = {};
    const float *Wp = nullptr, *Wa = nullptr, *Wo = nullptr, *Watt = nullptr;
    int nv = 0, np = 0, n60 = 0, n30 = 0;
    for (int i = 0; i < n_in; i++) {
        switch (in_sizes[i]) {
            case 800000: points = (const float*)d_in[i]; break;
            case 600000: if (nv < 5) io.vlc[nv++] = (const float*)d_in[i]; break;
            case 200000: if (np < 5) io.pv[np++] = (const int*)d_in[i]; break;
            case 120000: vfs[0] = (const int*)d_in[i]; break;
            case 60000:  vfs[n60 ? 3 : 1] = (const int*)d_in[i]; n60++; break;
            case 30000:  vfs[n30 ? 4 : 2] = (const int*)d_in[i]; n30++; break;
            case 576:    Wp = (const float*)d_in[i]; break;
            case 1152:   Wa = (const float*)d_in[i]; break;
            case 49152:  Wo = (const float*)d_in[i]; break;
            case 2304:   Watt = (const float*)d_in[i]; break;
            default: break;
        }
    }
    float* out = (float*)d_out;

    void* p_stats = nullptr;
    void* p_cur = nullptr;
    cudaGetSymbolAddress(&p_stats, g_stats);
    cudaGetSymbolAddress(&p_cur, g_cur);
    cudaFuncSetAttribute(k_gemm, cudaFuncAttributeMaxDynamicSharedMemorySize, 2 * GBUF);

    cudaMemsetAsync(d_out, 0, (size_t)out_size * sizeof(float));
    cudaMemsetAsync(p_stats, 0, 100000ull * 8 * sizeof(float));
    cudaMemsetAsync(p_cur, 0, 100000ull * sizeof(int));
    k_wcvt<<<96, 256>>>(Wo);
    k_statsfill<<<(NPTS + 255) / 256, 256>>>((const float4*)points, io);
    k_avfe<<<(NPTS + 255) / 256, 256>>>((const float4*)points, io, Wp, Wa);
    k_pvoxm<<<1095, 256>>>(Wo);
    k_gemm<<<(NPTS + 127) / 128, 256, 2 * GBUF>>>(io.pv[0], io.pv[1], io.pv[2]);
    k_out34v<<<3750, 256>>>((const float4*)points, io.vlc[3], io.vlc[4], Watt,
                            vfs[3], vfs[4], out);
}

// round 16
// speedup vs baseline: 1.2033x; 1.0102x over previous
#include <cuda_runtime.h>
#include <cuda_bf16.h>
#include <stdint.h>

#define NPTS 200000
#define FINFO_MIN_F (-3.4028234663852886e38f)

typedef unsigned long long ull;

// ---------------- scratch (device globals; no allocs allowed) ----------------
__device__ float g_stats[100000 * 8];            // per (scale,voxel): sums x,y,z,w, vlx,vly (count in g_cur)
__device__ int   g_cur[100000];                  // per (scale,voxel) point counter (= count)
__device__ int   g_plist[4800000];               // fixed-capacity point lists per (scale,voxel)
__device__ float g_P[70000 * 128];               // per-voxel vf @ W_o slice
__device__ float g_final[(size_t)200064 * 192];  // final0|final1|final2 per point (padded)
__device__ float g_pfco[(size_t)NPTS * 128];     // feat @ W_avfeo_point
__device__ uint4 g_Bcvt[7680];                   // Wo(final rows) as bf16 hi/lo smem images, 6 chunks

// ---------------- f32x2 / RED helpers ----------------
__device__ __forceinline__ ull dup2(float x) {
    ull r; asm("mov.b64 %0,{%1,%1};" : "=l"(r) : "f"(x)); return r;
}
__device__ __forceinline__ ull pk2(float x, float y) {
    ull r; asm("mov.b64 %0,{%1,%2};" : "=l"(r) : "f"(x), "f"(y)); return r;
}
__device__ __forceinline__ void fma2(ull& d, ull a, ull b) {
    asm("fma.rn.f32x2 %0,%1,%2,%0;" : "+l"(d) : "l"(a), "l"(b));
}
__device__ __forceinline__ ull mul2(ull a, ull b) {
    ull d; asm("mul.rn.f32x2 %0,%1,%2;" : "=l"(d) : "l"(a), "l"(b)); return d;
}
__device__ __forceinline__ void up2(float& x, float& y, ull a) {
    asm("mov.b64 {%0,%1},%2;" : "=f"(x), "=f"(y) : "l"(a));
}
__device__ __forceinline__ void redadd4(float* p, float a, float b, float c, float d) {
    asm volatile("red.global.add.v4.f32 [%0], {%1,%2,%3,%4};"
                 :: "l"(__cvta_generic_to_global(p)), "f"(a), "f"(b), "f"(c), "f"(d) : "memory");
}
__device__ __forceinline__ void redadd2(float* p, float a, float b) {
    asm volatile("red.global.add.v2.f32 [%0], {%1,%2};"
                 :: "l"(__cvta_generic_to_global(p)), "f"(a), "f"(b) : "memory");
}

// ---------------- mma / cp.async helpers ----------------
__device__ __forceinline__ uint32_t smem_u32(const void* p) {
    uint32_t a;
    asm("{ .reg .u64 t; cvta.to.shared.u64 t, %1; cvt.u32.u64 %0, t; }" : "=r"(a) : "l"(p));
    return a;
}
__device__ __forceinline__ void ldsm4(uint32_t* r, uint32_t addr) {
    asm volatile("ldmatrix.sync.aligned.m8n8.x4.shared.b16 {%0,%1,%2,%3}, [%4];"
                 : "=r"(r[0]), "=r"(r[1]), "=r"(r[2]), "=r"(r[3]) : "r"(addr));
}
__device__ __forceinline__ void mma_bf16(float* d, const uint32_t* a, uint32_t b0, uint32_t b1) {
    asm volatile(
        "mma.sync.aligned.m16n8k16.row.col.f32.bf16.bf16.f32 "
        "{%0,%1,%2,%3}, {%4,%5,%6,%7}, {%8,%9}, {%0,%1,%2,%3};"
        : "+f"(d[0]), "+f"(d[1]), "+f"(d[2]), "+f"(d[3])
        : "r"(a[0]), "r"(a[1]), "r"(a[2]), "r"(a[3]), "r"(b0), "r"(b1));
}
__device__ __forceinline__ void cpasync16(uint32_t smaddr, const void* g) {
    asm volatile("cp.async.ca.shared.global [%0], [%1], 16;"
                 :: "r"(smaddr), "l"(g) : "memory");
}
#define CP_COMMIT() asm volatile("cp.async.commit_group;" ::: "memory")
#define CP_WAIT0()  asm volatile("cp.async.wait_group 0;" ::: "memory")

__device__ __forceinline__ void cvt8(const float* x, uint4& hi, uint4& lo) {
    unsigned h[4], l[4];
    #pragma unroll
    for (int i = 0; i < 4; i++) {
        __nv_bfloat162 hb = __floats2bfloat162_rn(x[2 * i], x[2 * i + 1]);
        float f0 = __bfloat162float(hb.x), f1 = __bfloat162float(hb.y);
        __nv_bfloat162 lb = __floats2bfloat162_rn(x[2 * i] - f0, x[2 * i + 1] - f1);
        h[i] = *(unsigned*)&hb;
        l[i] = *(unsigned*)&lb;
    }
    hi.x = h[0]; hi.y = h[1]; hi.z = h[2]; hi.w = h[3];
    lo.x = l[0]; lo.y = l[1]; lo.z = l[2]; lo.w = l[3];
}

struct Ptrs {
    const float* vlc[5];
    const int*   pv[5];
};

// per-scale layout: soff {0,40000,60000,70000,90000}, cap {32,48,80,48,80},
// pbase {0,1280000,2240000,3040000,4000000}

// ---------------- per-voxel sums + point-list fill (blocks 0..781) + Wo cvt (blocks 782..877) ----------------
__global__ __launch_bounds__(256) void k_statsfill(const float4* __restrict__ pts, Ptrs io,
                                                   const float* __restrict__ Wo) {
    if (blockIdx.x >= 782) {
        // folded k_wcvt: Wo(final rows) -> bf16 hi/lo smem image
        int idx = (blockIdx.x - 782) * 256 + threadIdx.x;
        if (idx >= 192 * 128) return;
        int kk = idx >> 7, n = idx & 127;
        int kc = kk >> 5, ko = kk & 31;
        int r = ((kk >> 6) << 7) + (kk & 63);
        float v = Wo[(size_t)r * 128 + n];
        __nv_bfloat16 hb = __float2bfloat16_rn(v);
        __nv_bfloat16 lb = __float2bfloat16_rn(v - __bfloat162float(hb));
        char* base = (char*)g_Bcvt + kc * 20480 + n * 80 + ko * 2;
        *(__nv_bfloat16*)base = hb;
        *(__nv_bfloat16*)(base + 10240) = lb;
        return;
    }
    int p = blockIdx.x * 256 + threadIdx.x;
    if (p >= NPTS) return;
    float4 q = pts[p];
    const int soffs[5]  = {0, 40000, 60000, 70000, 90000};
    const int caps[5]   = {32, 48, 80, 48, 80};
    const int pbases[5] = {0, 1280000, 2240000, 3040000, 4000000};
    #pragma unroll
    for (int i = 0; i < 5; i++) {
        int v = io.pv[i][p];
        float vx = io.vlc[i][3 * p], vy = io.vlc[i][3 * p + 1];
        float* s = &g_stats[(size_t)(soffs[i] + v) * 8];
        redadd4(s, q.x, q.y, q.z, q.w);
        redadd2(s + 4, vx, vy);
        int slot = atomicAdd(&g_cur[soffs[i] + v], 1);
        if (slot < caps[i]) g_plist[pbases[i] + v * caps[i] + slot] = p;
    }
}

// ---------------- scales 0..2: folded-basis dual GEMV + product -> g_final ----------------
__global__ __launch_bounds__(256) void k_avfe(const float4* __restrict__ pts, Ptrs io,
                                              const float* __restrict__ Wp,
                                              const float* __restrict__ Wa) {
    __shared__ float sP[9 * 64];
    __shared__ float sA[12 * 64];
    const int tid = threadIdx.x;
    if (tid < 64) {
        const int c = tid;
        float w0 = Wp[c], w1 = Wp[64 + c], w2 = Wp[128 + c], w3 = Wp[192 + c];
        float w4 = Wp[256 + c], w5 = Wp[320 + c], w6 = Wp[384 + c], w7 = Wp[448 + c], w8 = Wp[512 + c];
        sP[0 * 64 + c] = w0 + w4; sP[1 * 64 + c] = w1 + w5; sP[2 * 64 + c] = w2 + w6;
        sP[3 * 64 + c] = w3;
        sP[4 * 64 + c] = -w4; sP[5 * 64 + c] = -w5; sP[6 * 64 + c] = -w6;
        sP[7 * 64 + c] = w7; sP[8 * 64 + c] = w8;
        float a0 = Wa[c], a1 = Wa[64 + c], a2 = Wa[128 + c], a3 = Wa[192 + c];
        float a4 = Wa[256 + c], a5 = Wa[320 + c], a6 = Wa[384 + c];
        float a7 = Wa[448 + c], a8 = Wa[512 + c];
        float a9 = Wa[576 + c], a10 = Wa[640 + c], a11 = Wa[704 + c], a12 = Wa[768 + c];
        float a16 = Wa[1024 + c], a17 = Wa[1088 + c];
        float L0 = a0 + a4, L1 = a1 + a5, L2 = a2 + a6;
        sA[0 * 64 + c] = L0; sA[1 * 64 + c] = L1; sA[2 * 64 + c] = L2; sA[3 * 64 + c] = a3;
        sA[4 * 64 + c] = a9 - L0; sA[5 * 64 + c] = a10 - L1; sA[6 * 64 + c] = a11 - L2;
        sA[7 * 64 + c] = a12;
        sA[8 * 64 + c] = a7; sA[9 * 64 + c] = a8;
        sA[10 * 64 + c] = a16; sA[11 * 64 + c] = a17;
    }
    __syncthreads();
    const int p = blockIdx.x * 256 + tid;
    if (p >= NPTS) return;
    float4 q = pts[p];
    ull cqx = dup2(q.x), cqy = dup2(q.y), cqz = dup2(q.z), cqw = dup2(q.w);
    #pragma unroll
    for (int i = 0; i < 3; i++) {
        const int soff = (i == 0) ? 0 : ((i == 1) ? 40000 : 60000);
        int v = io.pv[i][p];
        float vlx = io.vlc[i][3 * p], vly = io.vlc[i][3 * p + 1];
        const float4* s4 = (const float4*)&g_stats[(size_t)(soff + v) * 8];
        float4 sa = s4[0], sb = s4[1];
        float cntf = (float)g_cur[soff + v];
        float inv = 1.0f / fmaxf(cntf, 1.0f);
        ull cp4 = dup2(sa.x * inv), cp5 = dup2(sa.y * inv), cp6 = dup2(sa.z * inv), cp7 = dup2(sa.w * inv);
        ull cv0 = dup2(vlx), cv1 = dup2(vly);
        ull cm0 = dup2(sb.x * inv), cm1 = dup2(sb.y * inv);
        ull cp[9]  = {cqx, cqy, cqz, cqw, cp4, cp5, cp6, cv0, cv1};
        ull ca[12] = {cqx, cqy, cqz, cqw, cp4, cp5, cp6, cp7, cv0, cv1, cm0, cm1};
        float* fout = &g_final[(size_t)p * 192 + i * 64];
        #pragma unroll 2
        for (int c = 0; c < 64; c += 4) {
            ull p0 = 0, p1 = 0, a0 = 0, a1 = 0;
            #pragma unroll
            for (int r = 0; r < 9; r++) {
                ulonglong2 w = *(const ulonglong2*)&sP[r * 64 + c];
                fma2(p0, cp[r], w.x); fma2(p1, cp[r], w.y);
            }
            #pragma unroll
            for (int r = 0; r < 12; r++) {
                ulonglong2 w = *(const ulonglong2*)&sA[r * 64 + c];
                fma2(a0, ca[r], w.x); fma2(a1, ca[r], w.y);
            }
            ulonglong2 fo; fo.x = mul2(a0, p0); fo.y = mul2(a1, p1);
            *(ulonglong2*)&fout[c] = fo;
        }
    }
}

// ---------------- fused gather-max + GEMM: P = max_pts(final) @ W_o[vf-rows] ----------------
__global__ __launch_bounds__(256) void k_pvoxm(const float* __restrict__ Wo) {
    __shared__ float sA[64 * 68];
    const int b = blockIdx.x, tid = threadIdx.x;
    int voff, V, wrow, vb, cap, pbase, scoff;
    if (b < 625)      { voff = 0;     V = 40000; wrow = 64;  vb = b * 64;         cap = 32; pbase = 0;       scoff = 0; }
    else if (b < 938) { voff = 40000; V = 20000; wrow = 192; vb = (b - 625) * 64; cap = 48; pbase = 1280000; scoff = 64; }
    else              { voff = 60000; V = 10000; wrow = 320; vb = (b - 938) * 64; cap = 80; pbase = 2240000; scoff = 128; }
    {
        const int vl = tid >> 2, sub = tid & 3;
        const int v = vb + vl;
        float mx[16];
        #pragma unroll
        for (int c = 0; c < 16; c++) mx[c] = FINFO_MIN_F;
        if (v < V) {
            int cnt = g_cur[voff + v];
            if (cnt > cap) cnt = cap;
            const int* lst = &g_plist[pbase + v * cap];
            const int chb = sub * 16;
            int j = 0;
            for (; j + 2 <= cnt; j += 2) {
                int pA = lst[j], pB = lst[j + 1];
                const float4* fA = (const float4*)&g_final[(size_t)pA * 192 + scoff + chb];
                const float4* fB = (const float4*)&g_final[(size_t)pB * 192 + scoff + chb];
                float4 a0 = fA[0], a1 = fA[1], a2 = fA[2], a3 = fA[3];
                float4 b0 = fB[0], b1 = fB[1], b2 = fB[2], b3 = fB[3];
                mx[0] = fmaxf(mx[0], fmaxf(a0.x, b0.x)); mx[1] = fmaxf(mx[1], fmaxf(a0.y, b0.y));
                mx[2] = fmaxf(mx[2], fmaxf(a0.z, b0.z)); mx[3] = fmaxf(mx[3], fmaxf(a0.w, b0.w));
                mx[4] = fmaxf(mx[4], fmaxf(a1.x, b1.x)); mx[5] = fmaxf(mx[5], fmaxf(a1.y, b1.y));
                mx[6] = fmaxf(mx[6], fmaxf(a1.z, b1.z)); mx[7] = fmaxf(mx[7], fmaxf(a1.w, b1.w));
                mx[8] = fmaxf(mx[8], fmaxf(a2.x, b2.x)); mx[9] = fmaxf(mx[9], fmaxf(a2.y, b2.y));
                mx[10] = fmaxf(mx[10], fmaxf(a2.z, b2.z)); mx[11] = fmaxf(mx[11], fmaxf(a2.w, b2.w));
                mx[12] = fmaxf(mx[12], fmaxf(a3.x, b3.x)); mx[13] = fmaxf(mx[13], fmaxf(a3.y, b3.y));
                mx[14] = fmaxf(mx[14], fmaxf(a3.z, b3.z)); mx[15] = fmaxf(mx[15], fmaxf(a3.w, b3.w));
            }
            if (j < cnt) {
                int p = lst[j];
                const float4* f = (const float4*)&g_final[(size_t)p * 192 + scoff + chb];
                float4 x0 = f[0], x1 = f[1], x2 = f[2], x3 = f[3];
                mx[0] = fmaxf(mx[0], x0.x); mx[1] = fmaxf(mx[1], x0.y);
                mx[2] = fmaxf(mx[2], x0.z); mx[3] = fmaxf(mx[3], x0.w);
                mx[4] = fmaxf(mx[4], x1.x); mx[5] = fmaxf(mx[5], x1.y);
                mx[6] = fmaxf(mx[6], x1.z); mx[7] = fmaxf(mx[7], x1.w);
                mx[8] = fmaxf(mx[8], x2.x); mx[9] = fmaxf(mx[9], x2.y);
                mx[10] = fmaxf(mx[10], x2.z); mx[11] = fmaxf(mx[11], x2.w);
                mx[12] = fmaxf(mx[12], x3.x); mx[13] = fmaxf(mx[13], x3.y);
                mx[14] = fmaxf(mx[14], x3.z); mx[15] = fmaxf(mx[15], x3.w);
            }
        }
        const int chb = sub * 16;
        #pragma unroll
        for (int c = 0; c < 16; c++) sA[(chb + c) * 68 + vl] = mx[c];
    }
    __syncthreads();
    const int pg = tid >> 4, cg = tid & 15;
    const float* Wb = Wo + (size_t)wrow * 128 + cg * 8;
    ull acc[4][4] = {};
    #pragma unroll 8
    for (int k = 0; k < 64; k++) {
        float4 av = *(const float4*)&sA[k * 68 + pg * 4];
        ull a0 = dup2(av.x), a1 = dup2(av.y), a2 = dup2(av.z), a3 = dup2(av.w);
        const float* br = Wb + (size_t)k * 128;
        ulonglong2 b0 = *(const ulonglong2*)br;
        ulonglong2 b1 = *(const ulonglong2*)(br + 4);
        fma2(acc[0][0], a0, b0.x); fma2(acc[0][1], a0, b0.y); fma2(acc[0][2], a0, b1.x); fma2(acc[0][3], a0, b1.y);
        fma2(acc[1][0], a1, b0.x); fma2(acc[1][1], a1, b0.y); fma2(acc[1][2], a1, b1.x); fma2(acc[1][3], a1, b1.y);
        fma2(acc[2][0], a2, b0.x); fma2(acc[2][1], a2, b0.y); fma2(acc[2][2], a2, b1.x); fma2(acc[2][3], a2, b1.y);
        fma2(acc[3][0], a3, b0.x); fma2(acc[3][1], a3, b0.y); fma2(acc[3][2], a3, b1.x); fma2(acc[3][3], a3, b1.y);
    }
    #pragma unroll
    for (int m = 0; m < 4; m++) {
        int v = vb + pg * 4 + m;
        if (v < V) {
            float* dst = &g_P[(size_t)(voff + v) * 128 + cg * 8];
            ulonglong2 o0; o0.x = acc[m][0]; o0.y = acc[m][1];
            ulonglong2 o1; o1.x = acc[m][2]; o1.y = acc[m][3];
            *(ulonglong2*)dst = o0;
            *(ulonglong2*)(dst + 4) = o1;
        }
    }
}

// ---------------- main GEMM: mma.sync bf16 3-way split, K=192, 2x2 warp tile ----------------
// per buffer (40960 B): A_hi[128][40 bf16] @0, A_lo @10240, B_hi @20480, B_lo @30720
#define GBUF 40960

__device__ __forceinline__ void gemm_cvtstoreA(char* buf, const float* x, int srow, int sko) {
    uint4 h0, l0, h1, l1;
    cvt8(x, h0, l0); cvt8(x + 8, h1, l1);
    char* pa = buf + srow * 80 + sko * 2;
    *(uint4*)pa = h0;
    *(uint4*)(pa + 16) = h1;
    *(uint4*)(pa + 10240) = l0;
    *(uint4*)(pa + 10240 + 16) = l1;
}
__device__ __forceinline__ void gemm_loadA(float* x, int p0, int srow, int sko, int kc) {
    const float* src = &g_final[(size_t)(p0 + srow) * 192 + kc * 32 + sko];
    *(float4*)(x) = ((const float4*)src)[0];
    *(float4*)(x + 4) = ((const float4*)src)[1];
    *(float4*)(x + 8) = ((const float4*)src)[2];
    *(float4*)(x + 12) = ((const float4*)src)[3];
}
__device__ __forceinline__ void stageB_async(uint32_t dst, int kc, int tid) {
    const uint4* src = g_Bcvt + kc * 1280 + tid;
    #pragma unroll
    for (int i = 0; i < 5; i++)
        cpasync16(dst + (uint32_t)(tid + i * 256) * 16, src + i * 256);
}

__global__ __launch_bounds__(256, 2) void k_gemm(const int* __restrict__ pv0,
                                                 const int* __restrict__ pv1,
                                                 const int* __restrict__ pv2) {
    extern __shared__ __align__(16) char sm[];
    const int tid = threadIdx.x, lane = tid & 31, wid = tid >> 5;
    const int p0 = blockIdx.x * 128;
    const int mrow = (wid & 3) * 32;
    const int ncol = (wid >> 2) * 64;

    float acc[16][4] = {};
    const uint32_t abase = (uint32_t)((mrow + (lane & 15)) * 80 + ((lane >> 4) << 4));
    const uint32_t bbase = (uint32_t)(20480 + (ncol + (lane & 7) + ((lane >> 4) << 3)) * 80
                                      + ((lane & 8) << 1));
    const int srow = tid >> 1, sko = (tid & 1) * 16;

    float xa[16];
    {   // prologue: stage kc=0 (A cvt + B async), preload A(kc=1)
        float x0[16];
        gemm_loadA(x0, p0, srow, sko, 0);
        gemm_cvtstoreA(sm, x0, srow, sko);
        stageB_async(smem_u32(sm) + 20480, 0, tid);
        CP_COMMIT();
        gemm_loadA(xa, p0, srow, sko, 1);
        CP_WAIT0();
    }
    __syncthreads();

    for (int kc = 0; kc < 6; kc++) {
        const uint32_t cur = smem_u32(sm + (size_t)(kc & 1) * GBUF);
        #pragma unroll
        for (int s = 0; s < 2; s++) {
            uint32_t ah[2][4], al[2][4];
            #pragma unroll
            for (int mt = 0; mt < 2; mt++) {
                uint32_t aa = cur + abase + mt * 1280 + s * 32;
                ldsm4(ah[mt], aa);
                ldsm4(al[mt], aa + 10240);
            }
            #pragma unroll
            for (int np = 0; np < 4; np++) {
                uint32_t bb = cur + bbase + np * 1280 + s * 32;
                uint32_t bh[4], bl[4];
                ldsm4(bh, bb);
                ldsm4(bl, bb + 10240);
                #pragma unroll
                for (int mt = 0; mt < 2; mt++) {
                    const int t = mt * 8 + np * 2;
                    mma_bf16(acc[t],     ah[mt], bh[0], bh[1]);
                    mma_bf16(acc[t + 1], ah[mt], bh[2], bh[3]);
                    mma_bf16(acc[t],     ah[mt], bl[0], bl[1]);
                    mma_bf16(acc[t + 1], ah[mt], bl[2], bl[3]);
                    mma_bf16(acc[t],     al[mt], bh[0], bh[1]);
                    mma_bf16(acc[t + 1], al[mt], bh[2], bh[3]);
                }
            }
        }
        if (kc < 5) {
            char* nxt = sm + (size_t)((kc + 1) & 1) * GBUF;
            stageB_async(smem_u32(nxt) + 20480, kc + 1, tid);
            CP_COMMIT();
            gemm_cvtstoreA(nxt, xa, srow, sko);
            if (kc < 4) gemm_loadA(xa, p0, srow, sko, kc + 2);
            CP_WAIT0();
        }
        __syncthreads();
    }

    // epilogue: add P gathers, write pfco
    const int g = lane >> 2, c2 = (lane & 3) * 2;
    #pragma unroll
    for (int mt = 0; mt < 2; mt++) {
        #pragma unroll
        for (int r = 0; r < 2; r++) {
            const int p = p0 + mrow + mt * 16 + g + r * 8;
            if (p >= NPTS) continue;
            const int v0 = pv0[p], v1 = pv1[p], v2 = pv2[p];
            const float* P0 = &g_P[(size_t)v0 * 128];
            const float* P1 = &g_P[(size_t)(40000 + v1) * 128];
            const float* P2 = &g_P[(size_t)(60000 + v2) * 128];
            float* dst = &g_pfco[(size_t)p * 128];
            #pragma unroll
            for (int np = 0; np < 4; np++) {
                #pragma unroll
                for (int h = 0; h < 2; h++) {
                    const int t = mt * 8 + np * 2 + h;
                    const int col = ncol + np * 16 + h * 8 + c2;
                    float2 q0 = *(const float2*)(P0 + col);
                    float2 q1 = *(const float2*)(P1 + col);
                    float2 q2 = *(const float2*)(P2 + col);
                    float2 o;
                    o.x = acc[t][r * 2 + 0] + q0.x + q1.x + q2.x;
                    o.y = acc[t][r * 2 + 1] + q0.y + q1.y + q2.y;
                    *(float2*)(dst + col) = o;
                }
            }
        }
    }
}

// ---------------- scales 3..4: voxel-parallel gather, hoisted GEMV * pfc_o, max, scatter ----------------
__global__ __launch_bounds__(256) void k_out34v(const float4* __restrict__ pts,
                                                const float* __restrict__ vlc3,
                                                const float* __restrict__ vlc4,
                                                const float* __restrict__ Watt,
                                                const int* __restrict__ vfs3,
                                                const int* __restrict__ vfs4,
                                                float* __restrict__ out) {
    const int lane = threadIdx.x & 31, warp = threadIdx.x >> 5;
    ull wq[4][2], wv[2][2];
    ull wm[6][2];
    {
        const float* W = Watt + lane * 4;
        float4 w0 = *(const float4*)(W + 0 * 128), w1 = *(const float4*)(W + 1 * 128);
        float4 w2 = *(const float4*)(W + 2 * 128), w3 = *(const float4*)(W + 3 * 128);
        float4 w4 = *(const float4*)(W + 4 * 128), w5 = *(const float4*)(W + 5 * 128);
        float4 w6 = *(const float4*)(W + 6 * 128), w7 = *(const float4*)(W + 7 * 128);
        float4 w8 = *(const float4*)(W + 8 * 128), w9 = *(const float4*)(W + 9 * 128);
        float4 w10 = *(const float4*)(W + 10 * 128), w11 = *(const float4*)(W + 11 * 128);
        float4 w12 = *(const float4*)(W + 12 * 128);
        float4 w16 = *(const float4*)(W + 16 * 128), w17 = *(const float4*)(W + 17 * 128);
        float4 L0, L1, L2, R4, R5, R6;
        L0.x = w0.x + w4.x; L0.y = w0.y + w4.y; L0.z = w0.z + w4.z; L0.w = w0.w + w4.w;
        L1.x = w1.x + w5.x; L1.y = w1.y + w5.y; L1.z = w1.z + w5.z; L1.w = w1.w + w5.w;
        L2.x = w2.x + w6.x; L2.y = w2.y + w6.y; L2.z = w2.z + w6.z; L2.w = w2.w + w6.w;
        R4.x = w9.x - L0.x; R4.y = w9.y - L0.y; R4.z = w9.z - L0.z; R4.w = w9.w - L0.w;
        R5.x = w10.x - L1.x; R5.y = w10.y - L1.y; R5.z = w10.z - L1.z; R5.w = w10.w - L1.w;
        R6.x = w11.x - L2.x; R6.y = w11.y - L2.y; R6.z = w11.z - L2.z; R6.w = w11.w - L2.w;
        wq[0][0] = pk2(L0.x, L0.y);  wq[0][1] = pk2(L0.z, L0.w);
        wq[1][0] = pk2(L1.x, L1.y);  wq[1][1] = pk2(L1.z, L1.w);
        wq[2][0] = pk2(L2.x, L2.y);  wq[2][1] = pk2(L2.z, L2.w);
        wq[3][0] = pk2(w3.x, w3.y);  wq[3][1] = pk2(w3.z, w3.w);
        wm[0][0] = pk2(R4.x, R4.y);  wm[0][1] = pk2(R4.z, R4.w);
        wm[1][0] = pk2(R5.x, R5.y);  wm[1][1] = pk2(R5.z, R5.w);
        wm[2][0] = pk2(R6.x, R6.y);  wm[2][1] = pk2(R6.z, R6.w);
        wm[3][0] = pk2(w12.x, w12.y); wm[3][1] = pk2(w12.z, w12.w);
        wv[0][0] = pk2(w7.x, w7.y);  wv[0][1] = pk2(w7.z, w7.w);
        wv[1][0] = pk2(w8.x, w8.y);  wv[1][1] = pk2(w8.z, w8.w);
        wm[4][0] = pk2(w16.x, w16.y); wm[4][1] = pk2(w16.z, w16.w);
        wm[5][0] = pk2(w17.x, w17.y); wm[5][1] = pk2(w17.z, w17.w);
    }
    const int gw = blockIdx.x * 8 + warp;
    const int s = (gw >= 20000);
    const int v = s ? gw - 20000 : gw;
    const int soff = s ? 90000 : 70000;
    const int cap = s ? 80 : 48;
    const int pbase = s ? 4000000 : 3040000;
    const float* vlc = s ? vlc4 : vlc3;

    int cnt_raw = g_cur[soff + v];
    int cnt = cnt_raw > cap ? cap : cnt_raw;
    const int* lst = &g_plist[pbase + v * cap];

    const float4* s4 = (const float4*)&g_stats[(size_t)(soff + v) * 8];
    float4 sa = s4[0], sb = s4[1];
    float inv = 1.0f / fmaxf((float)cnt_raw, 1.0f);
    ull base0 = 0, base1 = 0;
    {
        ull cmv[6] = {dup2(sa.x * inv), dup2(sa.y * inv), dup2(sa.z * inv), dup2(sa.w * inv),
                      dup2(sb.x * inv), dup2(sb.y * inv)};
        #pragma unroll
        for (int r = 0; r < 6; r++) { fma2(base0, cmv[r], wm[r][0]); fma2(base1, cmv[r], wm[r][1]); }
    }

    float m0 = FINFO_MIN_F, m1 = FINFO_MIN_F, m2 = FINFO_MIN_F, m3 = FINFO_MIN_F;
    int j = 0;
    for (; j + 2 <= cnt; j += 2) {
        int pA = lst[j], pB = lst[j + 1];
        float4 qA = pts[pA], qB = pts[pB];
        float vlxA = vlc[3 * pA], vlyA = vlc[3 * pA + 1];
        float vlxB = vlc[3 * pB], vlyB = vlc[3 * pB + 1];
        ulonglong2 povA = *(const ulonglong2*)&g_pfco[(size_t)pA * 128 + lane * 4];
        ulonglong2 povB = *(const ulonglong2*)&g_pfco[(size_t)pB * 128 + lane * 4];
        {
            ull ca[6] = {dup2(qA.x), dup2(qA.y), dup2(qA.z), dup2(qA.w), dup2(vlxA), dup2(vlyA)};
            ull a0 = base0, a1 = base1;
            #pragma unroll
            for (int r = 0; r < 4; r++) { fma2(a0, ca[r], wq[r][0]); fma2(a1, ca[r], wq[r][1]); }
            fma2(a0, ca[4], wv[0][0]); fma2(a1, ca[4], wv[0][1]);
            fma2(a0, ca[5], wv[1][0]); fma2(a1, ca[5], wv[1][1]);
            ull f0 = mul2(a0, povA.x), f1 = mul2(a1, povA.y);
            float x0, x1, x2, x3;
            up2(x0, x1, f0); up2(x2, x3, f1);
            m0 = fmaxf(m0, x0); m1 = fmaxf(m1, x1); m2 = fmaxf(m2, x2); m3 = fmaxf(m3, x3);
        }
        {
            ull ca[6] = {dup2(qB.x), dup2(qB.y), dup2(qB.z), dup2(qB.w), dup2(vlxB), dup2(vlyB)};
            ull a0 = base0, a1 = base1;
            #pragma unroll
            for (int r = 0; r < 4; r++) { fma2(a0, ca[r], wq[r][0]); fma2(a1, ca[r], wq[r][1]); }
            fma2(a0, ca[4], wv[0][0]); fma2(a1, ca[4], wv[0][1]);
            fma2(a0, ca[5], wv[1][0]); fma2(a1, ca[5], wv[1][1]);
            ull f0 = mul2(a0, povB.x), f1 = mul2(a1, povB.y);
            float x0, x1, x2, x3;
            up2(x0, x1, f0); up2(x2, x3, f1);
            m0 = fmaxf(m0, x0); m1 = fmaxf(m1, x1); m2 = fmaxf(m2, x2); m3 = fmaxf(m3, x3);
        }
    }
    if (j < cnt) {
        int p = lst[j];
        float4 q = pts[p];
        float vlx = vlc[3 * p], vly = vlc[3 * p + 1];
        ulonglong2 pov = *(const ulonglong2*)&g_pfco[(size_t)p * 128 + lane * 4];
        ull ca[6] = {dup2(q.x), dup2(q.y), dup2(q.z), dup2(q.w), dup2(vlx), dup2(vly)};
        ull a0 = base0, a1 = base1;
        #pragma unroll
        for (int r = 0; r < 4; r++) { fma2(a0, ca[r], wq[r][0]); fma2(a1, ca[r], wq[r][1]); }
        fma2(a0, ca[4], wv[0][0]); fma2(a1, ca[4], wv[0][1]);
        fma2(a0, ca[5], wv[1][0]); fma2(a1, ca[5], wv[1][1]);
        ull f0 = mul2(a0, pov.x), f1 = mul2(a1, pov.y);
        float x0, x1, x2, x3;
        up2(x0, x1, f0); up2(x2, x3, f1);
        m0 = fmaxf(m0, x0); m1 = fmaxf(m1, x1); m2 = fmaxf(m2, x2); m3 = fmaxf(m3, x3);
    }
    const int* vr = s ? &vfs4[3 * v] : &vfs3[3 * v];
    int b_ = vr[0], y = vr[1], x = vr[2];
    const int HW = s ? 8836 : 35344;
    const int Wd = s ? 94 : 188;
    float* ob = s ? (out + (size_t)2 * 128 * 35344) : out;
    size_t base = ((size_t)b_ * 128 + lane * 4) * (size_t)HW + (size_t)y * Wd + x;
    ob[base] = m0;
    ob[base + HW] = m1;
    ob[base + 2 * (size_t)HW] = m2;
    ob[base + 3 * (size_t)HW] = m3;
}

// ---------------- host ----------------
extern "C" void kernel_launch(void* const* d_in, const int* in_sizes, int n_in,
                              void* d_out, int out_size) {
    const float* points = nullptr;
    Ptrs io = {};
    const int* vfs[5] = {};
    const float *Wp = nullptr, *Wa = nullptr, *Wo = nullptr, *Watt = nullptr;
    int nv = 0, np = 0, n60 = 0, n30 = 0;
    for (int i = 0; i < n_in; i++) {
        switch (in_sizes[i]) {
            case 800000: points = (const float*)d_in[i]; break;
            case 600000: if (nv < 5) io.vlc[nv++] = (const float*)d_in[i]; break;
            case 200000: if (np < 5) io.pv[np++] = (const int*)d_in[i]; break;
            case 120000: vfs[0] = (const int*)d_in[i]; break;
            case 60000:  vfs[n60 ? 3 : 1] = (const int*)d_in[i]; n60++; break;
            case 30000:  vfs[n30 ? 4 : 2] = (const int*)d_in[i]; n30++; break;
            case 576:    Wp = (const float*)d_in[i]; break;
            case 1152:   Wa = (const float*)d_in[i]; break;
            case 49152:  Wo = (const float*)d_in[i]; break;
            case 2304:   Watt = (const float*)d_in[i]; break;
            default: break;
        }
    }
    float* out = (float*)d_out;

    void* p_stats = nullptr;
    void* p_cur = nullptr;
    cudaGetSymbolAddress(&p_stats, g_stats);
    cudaGetSymbolAddress(&p_cur, g_cur);
    cudaFuncSetAttribute(k_gemm, cudaFuncAttributeMaxDynamicSharedMemorySize, 2 * GBUF);

    cudaMemsetAsync(d_out, 0, (size_t)out_size * sizeof(float));
    cudaMemsetAsync(p_stats, 0, 100000ull * 8 * sizeof(float));
    cudaMemsetAsync(p_cur, 0, 100000ull * sizeof(int));
    k_statsfill<<<878, 256>>>((const float4*)points, io, Wo);
    k_avfe<<<(NPTS + 255) / 256, 256>>>((const float4*)points, io, Wp, Wa);
    k_pvoxm<<<1095, 256>>>(Wo);
    k_gemm<<<(NPTS + 127) / 128, 256, 2 * GBUF>>>(io.pv[0], io.pv[1], io.pv[2]);
    k_out34v<<<3750, 256>>>((const float4*)points, io.vlc[3], io.vlc[4], Watt,
                            vfs[3], vfs[4], out);
}